// round 13
// baseline (speedup 1.0000x reference)
#include <cuda_runtime.h>
#include <cuda_bf16.h>
#include <cuda_fp16.h>
#include <cstdint>

#define DIM 128
#define CDIM 40
#define NLAYER 4
#define NMAX 50000
#define EMAX 800000
#define NSM 148

// ---------------- device scratch (static: no allocations allowed) ----------
__device__ float  g_xbuf[NMAX * DIM];     // fp32 residual
__device__ __half g_g16[NMAX * DIM];      // fp16 gather buffer (GEMM -> spmm)
__device__ __half g_h16[NMAX * DIM];      // fp16 spmm output (spmm -> GEMM)
__device__ float g_cs[2][DIM];            // PairNorm column sums (parity slots)
__device__ float g_cq[2][DIM];            // PairNorm column sumsq
__device__ float g_bn_ps[256][DIM];       // BN stats partials (no zero needed)
__device__ float g_bn_pq[256][DIM];
__device__ int   g_rowptr[NMAX + 1];
__device__ int   g_cnt[NMAX];             // invariant: zero between replays
__device__ int   g_wcur[NMAX];
__device__ int   g_bsum[256];
__device__ int2  g_edge[EMAX];            // (colidx, val-bits) packed

// ======================= helpers ===========================================
__device__ __forceinline__ uint32_t smem_u32(const void* p) {
    uint32_t a;
    asm("{ .reg .u64 t; cvta.to.shared.u64 t, %1; cvt.u32.u64 %0, t; }" : "=r"(a) : "l"(p));
    return a;
}
__device__ __forceinline__ void ldm_x4(uint32_t* r, uint32_t addr) {
    asm volatile("ldmatrix.sync.aligned.m8n8.x4.shared.b16 {%0,%1,%2,%3}, [%4];"
                 : "=r"(r[0]), "=r"(r[1]), "=r"(r[2]), "=r"(r[3]) : "r"(addr));
}
__device__ __forceinline__ void ldm_x4_t(uint32_t* r, uint32_t addr) {
    asm volatile("ldmatrix.sync.aligned.m8n8.x4.trans.shared.b16 {%0,%1,%2,%3}, [%4];"
                 : "=r"(r[0]), "=r"(r[1]), "=r"(r[2]), "=r"(r[3]) : "r"(addr));
}
__device__ __forceinline__ void mma_bf16(float* c, const uint32_t* a, const uint32_t* b) {
    asm volatile(
        "mma.sync.aligned.m16n8k16.row.col.f32.bf16.bf16.f32 "
        "{%0,%1,%2,%3}, {%4,%5,%6,%7}, {%8,%9}, {%0,%1,%2,%3};"
        : "+f"(c[0]), "+f"(c[1]), "+f"(c[2]), "+f"(c[3])
        : "r"(a[0]), "r"(a[1]), "r"(a[2]), "r"(a[3]), "r"(b[0]), "r"(b[1]));
}
__device__ __forceinline__ uint32_t pack_hi(float x, float y, uint32_t& lo) {
    __nv_bfloat16 hx = __float2bfloat16(x);
    __nv_bfloat16 hy = __float2bfloat16(y);
    __nv_bfloat16 lx = __float2bfloat16(x - __bfloat162float(hx));
    __nv_bfloat16 ly = __float2bfloat16(y - __bfloat162float(hy));
    lo = (uint32_t)__bfloat16_as_ushort(lx) | ((uint32_t)__bfloat16_as_ushort(ly) << 16);
    return (uint32_t)__bfloat16_as_ushort(hx) | ((uint32_t)__bfloat16_as_ushort(hy) << 16);
}
__device__ __forceinline__ float4 h4_to_f4(uint2 hv) {
    float2 lo = __half22float2(*reinterpret_cast<__half2*>(&hv.x));
    float2 hi = __half22float2(*reinterpret_cast<__half2*>(&hv.y));
    return make_float4(lo.x, lo.y, hi.x, hi.y);
}

// ======================= GEMM common pieces =================================
#define PADK 136
#define TILE_B (128 * PADK * 2)
#define OFF_AH 0
#define OFF_AL TILE_B
#define OFF_B1H (2 * TILE_B)
#define OFF_B1L (3 * TILE_B)
#define OFF_B2H (4 * TILE_B)
#define OFF_B2L (5 * TILE_B)
#define GEMM_SMEM_BYTES  (4 * TILE_B + 2048)
#define FUSED_SMEM_BYTES (6 * TILE_B + 2048)

__device__ __forceinline__ void mma_mainloop(uint32_t sb, int bOffH, int bOffL,
                                             int wm, int wn, int lane,
                                             float acc[2][4][4]) {
    int lrow = lane & 15;
    int lcol8 = (lane >> 4) << 3;
#pragma unroll
    for (int t = 0; t < 3; t++) {
        uint32_t aBase = sb + ((t == 2) ? OFF_AL : OFF_AH);
        uint32_t bBase = sb + ((t == 1) ? bOffL : bOffH);
#pragma unroll
        for (int k0 = 0; k0 < 128; k0 += 16) {
            uint32_t a[2][4];
#pragma unroll
            for (int mg = 0; mg < 2; mg++)
                ldm_x4(a[mg], aBase + (uint32_t)((wm + mg * 16 + lrow) * PADK + k0 + lcol8) * 2u);
            uint32_t b[2][4];
#pragma unroll
            for (int nc = 0; nc < 2; nc++)
                ldm_x4_t(b[nc], bBase + (uint32_t)((k0 + lrow) * PADK + wn + nc * 16 + lcol8) * 2u);
#pragma unroll
            for (int mg = 0; mg < 2; mg++)
#pragma unroll
                for (int ng = 0; ng < 4; ng++)
                    mma_bf16(acc[mg][ng], a[mg], &b[ng >> 1][(ng & 1) * 2]);
        }
    }
}

__device__ __forceinline__ void stage_B_f32(char* sm, int offH, int offL,
                                            const float* __restrict__ W,
                                            const float* rscale, int tid) {
    for (int g = tid; g < 4096; g += 512) {
        int r = g >> 5, c = (g & 31) * 4;
        float4 w = *reinterpret_cast<const float4*>(&W[r * DIM + c]);
        if (rscale) {
            float s = rscale[r];
            w.x *= s; w.y *= s; w.z *= s; w.w *= s;
        }
        uint32_t eoff = (uint32_t)(r * PADK + c) * 2u;
        uint32_t l0, l1;
        uint32_t h0 = pack_hi(w.x, w.y, l0);
        uint32_t h1 = pack_hi(w.z, w.w, l1);
        *reinterpret_cast<uint2*>(sm + offH + eoff) = make_uint2(h0, h1);
        *reinterpret_cast<uint2*>(sm + offL + eoff) = make_uint2(l0, l1);
    }
}

// ======================= main GEMM (persistent, fused PairNorm on A) ========
__global__ __launch_bounds__(512) void gemm_mma_k(
    const __half* __restrict__ A, const float* __restrict__ Xold,
    float* __restrict__ Xwrite, const float* __restrict__ Wf32,
    __half* __restrict__ C, int n,
    int pn_slot, int zero_slot, int addold, float n_inv) {
    extern __shared__ char sm[];
    float* smu = reinterpret_cast<float*>(sm + 4 * TILE_B);
    float* red = smu + DIM;
    uint32_t sb = smem_u32(sm);
    int tid = threadIdx.x, wid = tid >> 5, lane = tid & 31;

    if (zero_slot >= 0 && blockIdx.x == 0 && tid < DIM) {
        g_cs[zero_slot][tid] = 0.f;
        g_cq[zero_slot][tid] = 0.f;
    }

    if (tid < DIM) {
        float mu = g_cs[pn_slot][tid] * n_inv;
        smu[tid] = mu;
        red[tid] = g_cq[pn_slot][tid] * n_inv - mu * mu;
    }
    __syncthreads();
    for (int off = 64; off > 0; off >>= 1) {
        if (tid < off) red[tid] += red[tid + off];
        __syncthreads();
    }
    if (tid == 0) red[0] = rsqrtf(1e-6f + red[0]);
    __syncthreads();
    float pscale = red[0];

    int T = (n + 127) >> 7;
    int t = blockIdx.x;
    if (t >= T) return;

    stage_B_f32(sm, OFF_B1H, OFF_B1L, Wf32, nullptr, tid);

    {
        int row0 = t * 128;
        for (int g = tid; g < 4096; g += 512) {
            int r = g >> 5, c = (g & 31) * 4;
            int row = row0 + r;
            float4 av = make_float4(0.f, 0.f, 0.f, 0.f);
            if (row < n) {
                av = h4_to_f4(*reinterpret_cast<const uint2*>(&A[(size_t)row * DIM + c]));
                float4 m = *reinterpret_cast<const float4*>(&smu[c]);
                av.x = fmaxf((av.x - m.x) * pscale, 0.f);
                av.y = fmaxf((av.y - m.y) * pscale, 0.f);
                av.z = fmaxf((av.z - m.z) * pscale, 0.f);
                av.w = fmaxf((av.w - m.w) * pscale, 0.f);
                if (addold) {
                    float4 xo = *reinterpret_cast<const float4*>(&Xold[(size_t)row * DIM + c]);
                    av.x += xo.x; av.y += xo.y; av.z += xo.z; av.w += xo.w;
                }
                *reinterpret_cast<float4*>(&Xwrite[(size_t)row * DIM + c]) = av;
            }
            uint32_t eoff = (uint32_t)(r * PADK + c) * 2u;
            uint32_t al0, al1;
            uint32_t ah0 = pack_hi(av.x, av.y, al0);
            uint32_t ah1 = pack_hi(av.z, av.w, al1);
            *reinterpret_cast<uint2*>(sm + OFF_AH + eoff) = make_uint2(ah0, ah1);
            *reinterpret_cast<uint2*>(sm + OFF_AL + eoff) = make_uint2(al0, al1);
        }
    }
    __syncthreads();

    int wm = (wid & 3) * 32;
    int wn = (wid >> 2) * 32;

    while (true) {
        int tn = t + gridDim.x;
        bool hn = tn < T;
        uint2 raw[8];
        if (hn) {
            int row0n = tn * 128;
#pragma unroll
            for (int q = 0; q < 8; q++) {
                int g = q * 512 + tid;
                int r = g >> 5, c = (g & 31) * 4;
                int row = row0n + r;
                raw[q] = (row < n)
                    ? *reinterpret_cast<const uint2*>(&A[(size_t)row * DIM + c])
                    : make_uint2(0u, 0u);
            }
        }

        float acc[2][4][4];
#pragma unroll
        for (int mg = 0; mg < 2; mg++)
#pragma unroll
            for (int ng = 0; ng < 4; ng++)
#pragma unroll
                for (int q = 0; q < 4; q++) acc[mg][ng][q] = 0.f;

        mma_mainloop(sb, OFF_B1H, OFF_B1L, wm, wn, lane, acc);

        int row0 = t * 128;
        int rbase = row0 + wm + (lane >> 2);
        int cbase = wn + (lane & 3) * 2;
#pragma unroll
        for (int mg = 0; mg < 2; mg++)
#pragma unroll
            for (int half = 0; half < 2; half++) {
                int row = rbase + mg * 16 + half * 8;
                if (row < n) {
#pragma unroll
                    for (int ng = 0; ng < 4; ng++) {
                        int col = cbase + ng * 8;
                        __half2 o = __floats2half2_rn(acc[mg][ng][half * 2],
                                                      acc[mg][ng][half * 2 + 1]);
                        *reinterpret_cast<__half2*>(&C[(size_t)row * DIM + col]) = o;
                    }
                }
            }

        if (!hn) break;
        __syncthreads();
        {
            int row0n = tn * 128;
#pragma unroll
            for (int q = 0; q < 8; q++) {
                int g = q * 512 + tid;
                int r = g >> 5, c = (g & 31) * 4;
                int row = row0n + r;
                float4 av = make_float4(0.f, 0.f, 0.f, 0.f);
                if (row < n) {
                    av = h4_to_f4(raw[q]);
                    float4 m = *reinterpret_cast<const float4*>(&smu[c]);
                    av.x = fmaxf((av.x - m.x) * pscale, 0.f);
                    av.y = fmaxf((av.y - m.y) * pscale, 0.f);
                    av.z = fmaxf((av.z - m.z) * pscale, 0.f);
                    av.w = fmaxf((av.w - m.w) * pscale, 0.f);
                    if (addold) {
                        float4 xo = *reinterpret_cast<const float4*>(&Xold[(size_t)row * DIM + c]);
                        av.x += xo.x; av.y += xo.y; av.z += xo.z; av.w += xo.w;
                    }
                    *reinterpret_cast<float4*>(&Xwrite[(size_t)row * DIM + c]) = av;
                }
                uint32_t eoff = (uint32_t)(r * PADK + c) * 2u;
                uint32_t al0, al1;
                uint32_t ah0 = pack_hi(av.x, av.y, al0);
                uint32_t ah1 = pack_hi(av.z, av.w, al1);
                *reinterpret_cast<uint2*>(sm + OFF_AH + eoff) = make_uint2(ah0, ah1);
                *reinterpret_cast<uint2*>(sm + OFF_AL + eoff) = make_uint2(al0, al1);
            }
        }
        __syncthreads();
        t = tn;
    }
}

// ======================= fused fc_in + layer-0 GEMM (persistent) ============
__global__ __launch_bounds__(512) void gemm_fused_k(
    const float* __restrict__ X,
    const float* __restrict__ fin_w, const float* __restrict__ fin_b,
    const float* __restrict__ gamma, const float* __restrict__ beta,
    const float* __restrict__ W2,
    __half* __restrict__ C, int n, float n_inv) {
    extern __shared__ char sm[];
    float* ssc = reinterpret_cast<float*>(sm + 6 * TILE_B);
    float* ssh = ssc + DIM;
    float* sbias = ssh + DIM;
    uint32_t sb = smem_u32(sm);
    int tid = threadIdx.x, wid = tid >> 5, lane = tid & 31;

    if (blockIdx.x == 0 && tid < DIM) {
        g_cs[0][tid] = 0.f;
        g_cq[0][tid] = 0.f;
    }
    if (tid < DIM) {
        float s0 = 0.f, s1 = 0.f, s2 = 0.f, s3 = 0.f;
        float q0 = 0.f, q1 = 0.f, q2 = 0.f, q3 = 0.f;
        for (int p = 0; p < 256; p += 4) {
            s0 += g_bn_ps[p][tid];     s1 += g_bn_ps[p + 1][tid];
            s2 += g_bn_ps[p + 2][tid]; s3 += g_bn_ps[p + 3][tid];
            q0 += g_bn_pq[p][tid];     q1 += g_bn_pq[p + 1][tid];
            q2 += g_bn_pq[p + 2][tid]; q3 += g_bn_pq[p + 3][tid];
        }
        float mu = ((s0 + s1) + (s2 + s3)) * n_inv;
        float var = ((q0 + q1) + (q2 + q3)) * n_inv - mu * mu;
        float s = gamma[tid] * rsqrtf(var + 1e-5f);
        ssc[tid] = s;
        ssh[tid] = beta[tid] - mu * s;
    }
    __syncthreads();

    int T = (n + 127) >> 7;
    int t = blockIdx.x;
    if (t >= T) return;

    stage_B_f32(sm, OFF_B1H, OFF_B1L, fin_w, ssc, tid);
    stage_B_f32(sm, OFF_B2H, OFF_B2L, W2, nullptr, tid);
    if (tid < DIM) {
        float acc = fin_b[tid];
        for (int d = 0; d < DIM; d++) acc += ssh[d] * fin_w[d * DIM + tid];
        sbias[tid] = acc;
    }

    {
        int row0 = t * 128;
        for (int g = tid; g < 4096; g += 512) {
            int r = g >> 5, c = (g & 31) * 4;
            int row = row0 + r;
            float4 av = make_float4(0.f, 0.f, 0.f, 0.f);
            if (row < n) av = *reinterpret_cast<const float4*>(&X[(size_t)row * DIM + c]);
            uint32_t eoff = (uint32_t)(r * PADK + c) * 2u;
            uint32_t al0, al1;
            uint32_t ah0 = pack_hi(av.x, av.y, al0);
            uint32_t ah1 = pack_hi(av.z, av.w, al1);
            *reinterpret_cast<uint2*>(sm + OFF_AH + eoff) = make_uint2(ah0, ah1);
            *reinterpret_cast<uint2*>(sm + OFF_AL + eoff) = make_uint2(al0, al1);
        }
    }
    __syncthreads();

    int wm = (wid & 3) * 32;
    int wn = (wid >> 2) * 32;

    while (true) {
        int tn = t + gridDim.x;
        bool hn = tn < T;
        float4 raw[8];
        if (hn) {
            int row0n = tn * 128;
#pragma unroll
            for (int q = 0; q < 8; q++) {
                int g = q * 512 + tid;
                int r = g >> 5, c = (g & 31) * 4;
                int row = row0n + r;
                raw[q] = (row < n)
                    ? *reinterpret_cast<const float4*>(&X[(size_t)row * DIM + c])
                    : make_float4(0.f, 0.f, 0.f, 0.f);
            }
        }

        float acc[2][4][4];
#pragma unroll
        for (int mg = 0; mg < 2; mg++)
#pragma unroll
            for (int ng = 0; ng < 4; ng++)
#pragma unroll
                for (int q = 0; q < 4; q++) acc[mg][ng][q] = 0.f;

        mma_mainloop(sb, OFF_B1H, OFF_B1L, wm, wn, lane, acc);
        __syncthreads();

        {
            int rl = wm + (lane >> 2);
            int cb = wn + (lane & 3) * 2;
#pragma unroll
            for (int mg = 0; mg < 2; mg++)
#pragma unroll
                for (int half = 0; half < 2; half++) {
                    int r = rl + mg * 16 + half * 8;
#pragma unroll
                    for (int ng = 0; ng < 4; ng++) {
                        int col = cb + ng * 8;
                        float v0 = acc[mg][ng][half * 2] + sbias[col];
                        float v1 = acc[mg][ng][half * 2 + 1] + sbias[col + 1];
                        uint32_t lo;
                        uint32_t hi = pack_hi(v0, v1, lo);
                        uint32_t eoff = (uint32_t)(r * PADK + col) * 2u;
                        *reinterpret_cast<uint32_t*>(sm + OFF_AH + eoff) = hi;
                        *reinterpret_cast<uint32_t*>(sm + OFF_AL + eoff) = lo;
                    }
                }
        }
        __syncthreads();

#pragma unroll
        for (int mg = 0; mg < 2; mg++)
#pragma unroll
            for (int ng = 0; ng < 4; ng++)
#pragma unroll
                for (int q = 0; q < 4; q++) acc[mg][ng][q] = 0.f;

        mma_mainloop(sb, OFF_B2H, OFF_B2L, wm, wn, lane, acc);

        int row0 = t * 128;
        int rbase = row0 + wm + (lane >> 2);
        int cbase = wn + (lane & 3) * 2;
#pragma unroll
        for (int mg = 0; mg < 2; mg++)
#pragma unroll
            for (int half = 0; half < 2; half++) {
                int row = rbase + mg * 16 + half * 8;
                if (row < n) {
#pragma unroll
                    for (int ng = 0; ng < 4; ng++) {
                        int col = cbase + ng * 8;
                        __half2 o = __floats2half2_rn(acc[mg][ng][half * 2],
                                                      acc[mg][ng][half * 2 + 1]);
                        *reinterpret_cast<__half2*>(&C[(size_t)row * DIM + col]) = o;
                    }
                }
            }

        if (!hn) break;
        __syncthreads();
        {
#pragma unroll
            for (int q = 0; q < 8; q++) {
                int g = q * 512 + tid;
                int r = g >> 5, c = (g & 31) * 4;
                float4 av = raw[q];
                uint32_t eoff = (uint32_t)(r * PADK + c) * 2u;
                uint32_t al0, al1;
                uint32_t ah0 = pack_hi(av.x, av.y, al0);
                uint32_t ah1 = pack_hi(av.z, av.w, al1);
                *reinterpret_cast<uint2*>(sm + OFF_AH + eoff) = make_uint2(ah0, ah1);
                *reinterpret_cast<uint2*>(sm + OFF_AL + eoff) = make_uint2(al0, al1);
            }
        }
        __syncthreads();
        t = tn;
    }
}

// ======================= input BN stats -> per-block partials ===============
__global__ __launch_bounds__(256) void col_stats_k(const float* __restrict__ x, int n) {
    __shared__ float red[256];
    __shared__ float redq[128];
    int tid = threadIdx.x;
    red[tid] = 0.f;
    if (tid < 128) redq[tid] = 0.f;
    int w = tid >> 5, lane = tid & 31, c = lane * 4;
    int gw = blockIdx.x * 8 + w;
    const int STR = 256 * 8;
    float4 s = make_float4(0.f, 0.f, 0.f, 0.f);
    float4 q = make_float4(0.f, 0.f, 0.f, 0.f);
    __syncthreads();
    for (int r0 = gw; r0 < n; r0 += STR * 4) {
#pragma unroll
        for (int u = 0; u < 4; u++) {
            int row = r0 + u * STR;
            if (row < n) {
                float4 v = *reinterpret_cast<const float4*>(&x[(size_t)row * DIM + c]);
                s.x += v.x; s.y += v.y; s.z += v.z; s.w += v.w;
                q.x += v.x * v.x; q.y += v.y * v.y; q.z += v.z * v.z; q.w += v.w * v.w;
            }
        }
    }
    atomicAdd(&red[c], s.x);     atomicAdd(&red[c + 1], s.y);
    atomicAdd(&red[c + 2], s.z); atomicAdd(&red[c + 3], s.w);
    atomicAdd(&redq[c], q.x);     atomicAdd(&redq[c + 1], q.y);
    atomicAdd(&redq[c + 2], q.z); atomicAdd(&redq[c + 3], q.w);
    __syncthreads();
    if (tid < 128) {
        g_bn_ps[blockIdx.x][tid] = red[tid];
        g_bn_pq[blockIdx.x][tid] = redq[tid];
    }
}

// ======================= CSR build ==========================================
__global__ void hist_k(const int* __restrict__ er, int e) {
    int i = blockIdx.x * blockDim.x + threadIdx.x;
    if (i < e) atomicAdd(&g_cnt[er[i]], 1);
}

__global__ __launch_bounds__(256) void scan1_k(int n) {
    __shared__ int red[256];
    int tid = threadIdx.x;
    int i = blockIdx.x * 256 + tid;
    red[tid] = (i < n) ? g_cnt[i] : 0;
    __syncthreads();
    for (int off = 128; off > 0; off >>= 1) {
        if (tid < off) red[tid] += red[tid + off];
        __syncthreads();
    }
    if (tid == 0) g_bsum[blockIdx.x] = red[0];
}

__global__ __launch_bounds__(256) void scan3_k(int n, int nblk) {
    __shared__ int bs[256];
    __shared__ int s[256];
    int tid = threadIdx.x;
    bs[tid] = (tid < nblk) ? g_bsum[tid] : 0;
    __syncthreads();
    for (int off = 1; off < 256; off <<= 1) {
        int t = (tid >= off) ? bs[tid - off] : 0;
        __syncthreads();
        bs[tid] += t;
        __syncthreads();
    }
    int bpref = (blockIdx.x == 0) ? 0 : bs[blockIdx.x - 1];
    if (blockIdx.x == 0 && tid == 0) g_rowptr[n] = bs[255];
    int i = blockIdx.x * 256 + tid;
    int v = (i < n) ? g_cnt[i] : 0;
    s[tid] = v;
    __syncthreads();
    for (int off = 1; off < 256; off <<= 1) {
        int t = (tid >= off) ? s[tid - off] : 0;
        __syncthreads();
        s[tid] += t;
        __syncthreads();
    }
    if (i < n) {
        int excl = s[tid] - v + bpref;
        g_rowptr[i] = excl;
        g_wcur[i] = excl;
        g_cnt[i] = 0;
    }
}

__global__ void scatter_k(const int* __restrict__ er, const int* __restrict__ ec,
                          const float* __restrict__ ev, int e) {
    int i = blockIdx.x * blockDim.x + threadIdx.x;
    if (i < e) {
        int r = er[i];
        int pos = atomicAdd(&g_wcur[r], 1);
        g_edge[pos] = make_int2(ec[i], __float_as_int(ev[i]));
    }
}

// ======================= SPMM (fp16 in/out) + fused PairNorm stats ==========
// Warp owns 2 rows (doubled chip-wide warp count for more gathers in flight).
__global__ __launch_bounds__(256) void spmm_k(
    const __half* __restrict__ g, const float* __restrict__ bias,
    __half* __restrict__ h, int n, int slot) {
    __shared__ float red[256];
    int tid = threadIdx.x;
    red[tid] = 0.f;
    int w = tid >> 5, lane = tid & 31;
    int gw = blockIdx.x * 8 + w;
    int c = lane * 4;
    float4 b4 = *reinterpret_cast<const float4*>(&bias[c]);
    float4 ssum = make_float4(0.f, 0.f, 0.f, 0.f);
    float4 ssq = make_float4(0.f, 0.f, 0.f, 0.f);
    __syncthreads();
#pragma unroll
    for (int rr = 0; rr < 2; rr++) {
        int row = gw * 2 + rr;
        if (row >= n) break;
        int s = g_rowptr[row];
        int e = g_rowptr[row + 1];
        float4 acc = make_float4(0.f, 0.f, 0.f, 0.f);
        int i = s;
        for (; i + 7 < e; i += 8) {
            uint2 p[8];
            float vv[8];
#pragma unroll
            for (int u = 0; u < 8; u++) {
                int2 ed = g_edge[i + u];
                vv[u] = __int_as_float(ed.y);
                p[u] = *reinterpret_cast<const uint2*>(&g[(size_t)ed.x * DIM + c]);
            }
#pragma unroll
            for (int u = 0; u < 8; u++) {
                float4 gv = h4_to_f4(p[u]);
                acc.x += vv[u] * gv.x;
                acc.y += vv[u] * gv.y;
                acc.z += vv[u] * gv.z;
                acc.w += vv[u] * gv.w;
            }
        }
        if (i + 3 < e) {
            uint2 p[4];
            float vv[4];
#pragma unroll
            for (int u = 0; u < 4; u++) {
                int2 ed = g_edge[i + u];
                vv[u] = __int_as_float(ed.y);
                p[u] = *reinterpret_cast<const uint2*>(&g[(size_t)ed.x * DIM + c]);
            }
#pragma unroll
            for (int u = 0; u < 4; u++) {
                float4 gv = h4_to_f4(p[u]);
                acc.x += vv[u] * gv.x;
                acc.y += vv[u] * gv.y;
                acc.z += vv[u] * gv.z;
                acc.w += vv[u] * gv.w;
            }
            i += 4;
        }
        for (; i < e; i++) {
            int2 ed = g_edge[i];
            float v0 = __int_as_float(ed.y);
            float4 gv = h4_to_f4(*reinterpret_cast<const uint2*>(&g[(size_t)ed.x * DIM + c]));
            acc.x += v0 * gv.x; acc.y += v0 * gv.y;
            acc.z += v0 * gv.z; acc.w += v0 * gv.w;
        }
        acc.x += b4.x; acc.y += b4.y; acc.z += b4.z; acc.w += b4.w;
        __half2 o0 = __floats2half2_rn(acc.x, acc.y);
        __half2 o1 = __floats2half2_rn(acc.z, acc.w);
        uint2 ov;
        ov.x = *reinterpret_cast<uint32_t*>(&o0);
        ov.y = *reinterpret_cast<uint32_t*>(&o1);
        *reinterpret_cast<uint2*>(&h[(size_t)row * DIM + c]) = ov;
        ssum.x += acc.x; ssum.y += acc.y; ssum.z += acc.z; ssum.w += acc.w;
        ssq.x += acc.x * acc.x; ssq.y += acc.y * acc.y;
        ssq.z += acc.z * acc.z; ssq.w += acc.w * acc.w;
    }
    atomicAdd(&red[c], ssum.x);     atomicAdd(&red[c + 1], ssum.y);
    atomicAdd(&red[c + 2], ssum.z); atomicAdd(&red[c + 3], ssum.w);
    atomicAdd(&red[128 + c], ssq.x);     atomicAdd(&red[128 + c + 1], ssq.y);
    atomicAdd(&red[128 + c + 2], ssq.z); atomicAdd(&red[128 + c + 3], ssq.w);
    __syncthreads();
    if (tid < 128) atomicAdd(&g_cs[slot][tid], red[tid]);
    else atomicAdd(&g_cq[slot][tid - 128], red[tid]);
}

// ======================= output GEMM + fused final PairNorm =================
__global__ __launch_bounds__(256) void gemm_out_k(
    const __half* __restrict__ H, const float* __restrict__ Xold,
    const float* __restrict__ W, const float* __restrict__ b,
    float* __restrict__ out, int n, int pn_slot, float n_inv) {
    __shared__ float sx[32 * DIM];
    __shared__ float sw[DIM * CDIM];
    __shared__ float smu[DIM];
    __shared__ float red[DIM];
    int tid = threadIdx.x;
    int row0 = blockIdx.x * 32;
    for (int i = tid; i < DIM * CDIM; i += 256) sw[i] = W[i];
    if (tid < DIM) {
        float mu = g_cs[pn_slot][tid] * n_inv;
        smu[tid] = mu;
        red[tid] = g_cq[pn_slot][tid] * n_inv - mu * mu;
    }
    __syncthreads();
    for (int off = 64; off > 0; off >>= 1) {
        if (tid < off) red[tid] += red[tid + off];
        __syncthreads();
    }
    if (tid == 0) red[0] = rsqrtf(1e-6f + red[0]);
    __syncthreads();
    float s = red[0];
#pragma unroll
    for (int q = 0; q < 4; q++) {
        int flat = (q * 256 + tid) * 4;
        int r = flat >> 7, c = flat & 127;
        int row = row0 + r;
        float4 v = make_float4(0.f, 0.f, 0.f, 0.f);
        if (row < n) {
            float4 hv = h4_to_f4(*reinterpret_cast<const uint2*>(&H[(size_t)row * DIM + c]));
            float4 m = *reinterpret_cast<const float4*>(&smu[c]);
            float4 xo = *reinterpret_cast<const float4*>(&Xold[(size_t)row * DIM + c]);
            v.x = fmaxf((hv.x - m.x) * s, 0.f) + xo.x;
            v.y = fmaxf((hv.y - m.y) * s, 0.f) + xo.y;
            v.z = fmaxf((hv.z - m.z) * s, 0.f) + xo.z;
            v.w = fmaxf((hv.w - m.w) * s, 0.f) + xo.w;
        }
        *reinterpret_cast<float4*>(&sx[flat]) = v;
    }
    __syncthreads();
    int r = tid >> 3;
    int c0 = (tid & 7) * 5;
    float acc[5];
#pragma unroll
    for (int j = 0; j < 5; j++) acc[j] = b[c0 + j];
#pragma unroll 4
    for (int k = 0; k < DIM; k++) {
        float xv = sx[r * DIM + k];
#pragma unroll
        for (int j = 0; j < 5; j++) acc[j] += xv * sw[k * CDIM + c0 + j];
    }
    if (row0 + r < n) {
#pragma unroll
        for (int j = 0; j < 5; j++) out[(size_t)(row0 + r) * CDIM + c0 + j] = acc[j];
    }
}

// ======================= launch =============================================
extern "C" void kernel_launch(void* const* d_in, const int* in_sizes, int n_in,
                              void* d_out, int out_size) {
    const float* x      = (const float*)d_in[0];
    const int*   er     = (const int*)d_in[1];
    const int*   ec     = (const int*)d_in[2];
    const float* ev     = (const float*)d_in[3];
    const float* gamma  = (const float*)d_in[4];
    const float* beta   = (const float*)d_in[5];
    const float* fin_w  = (const float*)d_in[6];
    const float* fin_b  = (const float*)d_in[7];
    const float* gc_w   = (const float*)d_in[8];
    const float* gc_b   = (const float*)d_in[9];
    const float* fout_w = (const float*)d_in[10];
    const float* fout_b = (const float*)d_in[11];
    float* out = (float*)d_out;

    int n = in_sizes[0] / DIM;
    int e = in_sizes[1];
    float n_inv = 1.0f / (float)n;

    float* xbuf;
    __half *g16, *h16;
    cudaGetSymbolAddress((void**)&xbuf, g_xbuf);
    cudaGetSymbolAddress((void**)&g16, g_g16);
    cudaGetSymbolAddress((void**)&h16, g_h16);

    static cudaStream_t s2 = nullptr;
    static cudaEvent_t evFork = nullptr, evJoin = nullptr;
    if (s2 == nullptr) {
        cudaStreamCreateWithFlags(&s2, cudaStreamNonBlocking);
        cudaEventCreateWithFlags(&evFork, cudaEventDisableTiming);
        cudaEventCreateWithFlags(&evJoin, cudaEventDisableTiming);
        cudaFuncSetAttribute(gemm_mma_k, cudaFuncAttributeMaxDynamicSharedMemorySize, GEMM_SMEM_BYTES);
        cudaFuncSetAttribute(gemm_fused_k, cudaFuncAttributeMaxDynamicSharedMemorySize, FUSED_SMEM_BYTES);
    }

    int sblocks = (n + 15) / 16;     // spmm: warp owns 2 rows
    int nblk = (n + 255) / 256;
    int eblk = (e + 255) / 256;
    const int WMAT = DIM * DIM;

    // ---- fork before anything; branch B waits only on evFork (empty main) --
    cudaEventRecord(evFork, 0);
    cudaStreamWaitEvent(s2, evFork, 0);

    // main stream: CSR build (launch indices 1-4 for ncu -s 5)
    hist_k<<<eblk, 256>>>(er, e);
    scan1_k<<<nblk, 256>>>(n);
    scan3_k<<<nblk, 256>>>(n, nblk);
    scatter_k<<<eblk, 256>>>(er, ec, ev, e);

    // branch B (stream s2): col_stats (5), gemm_fused (6 -> profiled)
    col_stats_k<<<256, 256, 0, s2>>>(x, n);
    gemm_fused_k<<<NSM, 512, FUSED_SMEM_BYTES, s2>>>(
        x, fin_w, fin_b, gamma, beta, gc_w, g16, n, n_inv);

    // ---- join
    cudaEventRecord(evJoin, s2);
    cudaStreamWaitEvent(0, evJoin, 0);

    // ---- layer 0 spmm ----
    spmm_k<<<sblocks, 256>>>(g16, gc_b + 0 * DIM, h16, n, 0);

    // ---- layers 1..3: persistent GEMM with fused PairNorm-apply on A ----
    for (int i = 1; i < NLAYER; i++) {
        gemm_mma_k<<<NSM, 512, GEMM_SMEM_BYTES>>>(
            h16, xbuf, xbuf, gc_w + i * WMAT,
            g16, n, (i - 1) & 1, i & 1, (i >= 2) ? 1 : 0, n_inv);
        spmm_k<<<sblocks, 256>>>(g16, gc_b + i * DIM, h16, n, i & 1);
    }

    // ---- output projection with fused final PairNorm (slot 1, addold) ----
    gemm_out_k<<<sblocks * 2, 256>>>(h16, xbuf, fout_w, fout_b, out, n, (NLAYER - 1) & 1, n_inv);
}

// round 14
// speedup vs baseline: 1.2426x; 1.2426x over previous
#include <cuda_runtime.h>
#include <cuda_bf16.h>
#include <cuda_fp16.h>
#include <cstdint>

#define DIM 128
#define CDIM 40
#define NLAYER 4
#define NMAX 50000
#define EMAX 800000
#define NSM 148

// ---------------- device scratch (static: no allocations allowed) ----------
__device__ float  g_xbuf[NMAX * DIM];     // fp32 residual
__device__ __half g_g16[NMAX * DIM];      // fp16 gather buffer (GEMM -> spmm)
__device__ __half g_h16[NMAX * DIM];      // fp16 spmm output (spmm -> GEMM)
__device__ float g_cs[2][DIM];            // PairNorm column sums (parity slots)
__device__ float g_cq[2][DIM];            // PairNorm column sumsq
__device__ float g_bn_ps[256][DIM];       // BN stats partials (no zero needed)
__device__ float g_bn_pq[256][DIM];
__device__ int   g_rowptr[NMAX + 1];
__device__ int   g_cnt[NMAX];             // invariant: zero between replays
__device__ int   g_wcur[NMAX];
__device__ int   g_bsum[256];
__device__ int2  g_edge[EMAX];            // (colidx, val-bits) packed

// ======================= helpers ===========================================
__device__ __forceinline__ uint32_t smem_u32(const void* p) {
    uint32_t a;
    asm("{ .reg .u64 t; cvta.to.shared.u64 t, %1; cvt.u32.u64 %0, t; }" : "=r"(a) : "l"(p));
    return a;
}
__device__ __forceinline__ void ldm_x4(uint32_t* r, uint32_t addr) {
    asm volatile("ldmatrix.sync.aligned.m8n8.x4.shared.b16 {%0,%1,%2,%3}, [%4];"
                 : "=r"(r[0]), "=r"(r[1]), "=r"(r[2]), "=r"(r[3]) : "r"(addr));
}
__device__ __forceinline__ void ldm_x4_t(uint32_t* r, uint32_t addr) {
    asm volatile("ldmatrix.sync.aligned.m8n8.x4.trans.shared.b16 {%0,%1,%2,%3}, [%4];"
                 : "=r"(r[0]), "=r"(r[1]), "=r"(r[2]), "=r"(r[3]) : "r"(addr));
}
__device__ __forceinline__ void mma_bf16(float* c, const uint32_t* a, const uint32_t* b) {
    asm volatile(
        "mma.sync.aligned.m16n8k16.row.col.f32.bf16.bf16.f32 "
        "{%0,%1,%2,%3}, {%4,%5,%6,%7}, {%8,%9}, {%0,%1,%2,%3};"
        : "+f"(c[0]), "+f"(c[1]), "+f"(c[2]), "+f"(c[3])
        : "r"(a[0]), "r"(a[1]), "r"(a[2]), "r"(a[3]), "r"(b[0]), "r"(b[1]));
}
__device__ __forceinline__ uint32_t pack_hi(float x, float y, uint32_t& lo) {
    __nv_bfloat16 hx = __float2bfloat16(x);
    __nv_bfloat16 hy = __float2bfloat16(y);
    __nv_bfloat16 lx = __float2bfloat16(x - __bfloat162float(hx));
    __nv_bfloat16 ly = __float2bfloat16(y - __bfloat162float(hy));
    lo = (uint32_t)__bfloat16_as_ushort(lx) | ((uint32_t)__bfloat16_as_ushort(ly) << 16);
    return (uint32_t)__bfloat16_as_ushort(hx) | ((uint32_t)__bfloat16_as_ushort(hy) << 16);
}
__device__ __forceinline__ float4 h4_to_f4(uint2 hv) {
    float2 lo = __half22float2(*reinterpret_cast<__half2*>(&hv.x));
    float2 hi = __half22float2(*reinterpret_cast<__half2*>(&hv.y));
    return make_float4(lo.x, lo.y, hi.x, hi.y);
}

// ======================= GEMM common pieces =================================
#define PADK 136
#define TILE_B (128 * PADK * 2)
#define OFF_AH 0
#define OFF_AL TILE_B
#define OFF_B1H (2 * TILE_B)
#define OFF_B1L (3 * TILE_B)
#define OFF_B2H (4 * TILE_B)
#define OFF_B2L (5 * TILE_B)
#define GEMM_SMEM_BYTES  (4 * TILE_B + 2048)
#define FUSED_SMEM_BYTES (6 * TILE_B + 2048)

__device__ __forceinline__ void mma_mainloop(uint32_t sb, int bOffH, int bOffL,
                                             int wm, int wn, int lane,
                                             float acc[2][4][4]) {
    int lrow = lane & 15;
    int lcol8 = (lane >> 4) << 3;
#pragma unroll
    for (int t = 0; t < 3; t++) {
        uint32_t aBase = sb + ((t == 2) ? OFF_AL : OFF_AH);
        uint32_t bBase = sb + ((t == 1) ? bOffL : bOffH);
#pragma unroll
        for (int k0 = 0; k0 < 128; k0 += 16) {
            uint32_t a[2][4];
#pragma unroll
            for (int mg = 0; mg < 2; mg++)
                ldm_x4(a[mg], aBase + (uint32_t)((wm + mg * 16 + lrow) * PADK + k0 + lcol8) * 2u);
            uint32_t b[2][4];
#pragma unroll
            for (int nc = 0; nc < 2; nc++)
                ldm_x4_t(b[nc], bBase + (uint32_t)((k0 + lrow) * PADK + wn + nc * 16 + lcol8) * 2u);
#pragma unroll
            for (int mg = 0; mg < 2; mg++)
#pragma unroll
                for (int ng = 0; ng < 4; ng++)
                    mma_bf16(acc[mg][ng], a[mg], &b[ng >> 1][(ng & 1) * 2]);
        }
    }
}

__device__ __forceinline__ void stage_B_f32(char* sm, int offH, int offL,
                                            const float* __restrict__ W,
                                            const float* rscale, int tid) {
    for (int g = tid; g < 4096; g += 512) {
        int r = g >> 5, c = (g & 31) * 4;
        float4 w = *reinterpret_cast<const float4*>(&W[r * DIM + c]);
        if (rscale) {
            float s = rscale[r];
            w.x *= s; w.y *= s; w.z *= s; w.w *= s;
        }
        uint32_t eoff = (uint32_t)(r * PADK + c) * 2u;
        uint32_t l0, l1;
        uint32_t h0 = pack_hi(w.x, w.y, l0);
        uint32_t h1 = pack_hi(w.z, w.w, l1);
        *reinterpret_cast<uint2*>(sm + offH + eoff) = make_uint2(h0, h1);
        *reinterpret_cast<uint2*>(sm + offL + eoff) = make_uint2(l0, l1);
    }
}

// ======================= main GEMM (persistent, fused PairNorm on A) ========
__global__ __launch_bounds__(512) void gemm_mma_k(
    const __half* __restrict__ A, const float* __restrict__ Xold,
    float* __restrict__ Xwrite, const float* __restrict__ Wf32,
    __half* __restrict__ C, int n,
    int pn_slot, int zero_slot, int addold, float n_inv) {
    extern __shared__ char sm[];
    float* smu = reinterpret_cast<float*>(sm + 4 * TILE_B);
    float* red = smu + DIM;
    uint32_t sb = smem_u32(sm);
    int tid = threadIdx.x, wid = tid >> 5, lane = tid & 31;

    if (zero_slot >= 0 && blockIdx.x == 0 && tid < DIM) {
        g_cs[zero_slot][tid] = 0.f;
        g_cq[zero_slot][tid] = 0.f;
    }

    if (tid < DIM) {
        float mu = g_cs[pn_slot][tid] * n_inv;
        smu[tid] = mu;
        red[tid] = g_cq[pn_slot][tid] * n_inv - mu * mu;
    }
    __syncthreads();
    for (int off = 64; off > 0; off >>= 1) {
        if (tid < off) red[tid] += red[tid + off];
        __syncthreads();
    }
    if (tid == 0) red[0] = rsqrtf(1e-6f + red[0]);
    __syncthreads();
    float pscale = red[0];

    int T = (n + 127) >> 7;
    int t = blockIdx.x;
    if (t >= T) return;

    stage_B_f32(sm, OFF_B1H, OFF_B1L, Wf32, nullptr, tid);

    {
        int row0 = t * 128;
        for (int g = tid; g < 4096; g += 512) {
            int r = g >> 5, c = (g & 31) * 4;
            int row = row0 + r;
            float4 av = make_float4(0.f, 0.f, 0.f, 0.f);
            if (row < n) {
                av = h4_to_f4(*reinterpret_cast<const uint2*>(&A[(size_t)row * DIM + c]));
                float4 m = *reinterpret_cast<const float4*>(&smu[c]);
                av.x = fmaxf((av.x - m.x) * pscale, 0.f);
                av.y = fmaxf((av.y - m.y) * pscale, 0.f);
                av.z = fmaxf((av.z - m.z) * pscale, 0.f);
                av.w = fmaxf((av.w - m.w) * pscale, 0.f);
                if (addold) {
                    float4 xo = *reinterpret_cast<const float4*>(&Xold[(size_t)row * DIM + c]);
                    av.x += xo.x; av.y += xo.y; av.z += xo.z; av.w += xo.w;
                }
                *reinterpret_cast<float4*>(&Xwrite[(size_t)row * DIM + c]) = av;
            }
            uint32_t eoff = (uint32_t)(r * PADK + c) * 2u;
            uint32_t al0, al1;
            uint32_t ah0 = pack_hi(av.x, av.y, al0);
            uint32_t ah1 = pack_hi(av.z, av.w, al1);
            *reinterpret_cast<uint2*>(sm + OFF_AH + eoff) = make_uint2(ah0, ah1);
            *reinterpret_cast<uint2*>(sm + OFF_AL + eoff) = make_uint2(al0, al1);
        }
    }
    __syncthreads();

    int wm = (wid & 3) * 32;
    int wn = (wid >> 2) * 32;

    while (true) {
        int tn = t + gridDim.x;
        bool hn = tn < T;
        uint2 raw[8];
        if (hn) {
            int row0n = tn * 128;
#pragma unroll
            for (int q = 0; q < 8; q++) {
                int g = q * 512 + tid;
                int r = g >> 5, c = (g & 31) * 4;
                int row = row0n + r;
                raw[q] = (row < n)
                    ? *reinterpret_cast<const uint2*>(&A[(size_t)row * DIM + c])
                    : make_uint2(0u, 0u);
            }
        }

        float acc[2][4][4];
#pragma unroll
        for (int mg = 0; mg < 2; mg++)
#pragma unroll
            for (int ng = 0; ng < 4; ng++)
#pragma unroll
                for (int q = 0; q < 4; q++) acc[mg][ng][q] = 0.f;

        mma_mainloop(sb, OFF_B1H, OFF_B1L, wm, wn, lane, acc);

        int row0 = t * 128;
        int rbase = row0 + wm + (lane >> 2);
        int cbase = wn + (lane & 3) * 2;
#pragma unroll
        for (int mg = 0; mg < 2; mg++)
#pragma unroll
            for (int half = 0; half < 2; half++) {
                int row = rbase + mg * 16 + half * 8;
                if (row < n) {
#pragma unroll
                    for (int ng = 0; ng < 4; ng++) {
                        int col = cbase + ng * 8;
                        __half2 o = __floats2half2_rn(acc[mg][ng][half * 2],
                                                      acc[mg][ng][half * 2 + 1]);
                        *reinterpret_cast<__half2*>(&C[(size_t)row * DIM + col]) = o;
                    }
                }
            }

        if (!hn) break;
        __syncthreads();
        {
            int row0n = tn * 128;
#pragma unroll
            for (int q = 0; q < 8; q++) {
                int g = q * 512 + tid;
                int r = g >> 5, c = (g & 31) * 4;
                int row = row0n + r;
                float4 av = make_float4(0.f, 0.f, 0.f, 0.f);
                if (row < n) {
                    av = h4_to_f4(raw[q]);
                    float4 m = *reinterpret_cast<const float4*>(&smu[c]);
                    av.x = fmaxf((av.x - m.x) * pscale, 0.f);
                    av.y = fmaxf((av.y - m.y) * pscale, 0.f);
                    av.z = fmaxf((av.z - m.z) * pscale, 0.f);
                    av.w = fmaxf((av.w - m.w) * pscale, 0.f);
                    if (addold) {
                        float4 xo = *reinterpret_cast<const float4*>(&Xold[(size_t)row * DIM + c]);
                        av.x += xo.x; av.y += xo.y; av.z += xo.z; av.w += xo.w;
                    }
                    *reinterpret_cast<float4*>(&Xwrite[(size_t)row * DIM + c]) = av;
                }
                uint32_t eoff = (uint32_t)(r * PADK + c) * 2u;
                uint32_t al0, al1;
                uint32_t ah0 = pack_hi(av.x, av.y, al0);
                uint32_t ah1 = pack_hi(av.z, av.w, al1);
                *reinterpret_cast<uint2*>(sm + OFF_AH + eoff) = make_uint2(ah0, ah1);
                *reinterpret_cast<uint2*>(sm + OFF_AL + eoff) = make_uint2(al0, al1);
            }
        }
        __syncthreads();
        t = tn;
    }
}

// ======================= fused fc_in + layer-0 GEMM (persistent) ============
__global__ __launch_bounds__(512) void gemm_fused_k(
    const float* __restrict__ X,
    const float* __restrict__ fin_w, const float* __restrict__ fin_b,
    const float* __restrict__ gamma, const float* __restrict__ beta,
    const float* __restrict__ W2,
    __half* __restrict__ C, int n, float n_inv) {
    extern __shared__ char sm[];
    float* ssc = reinterpret_cast<float*>(sm + 6 * TILE_B);
    float* ssh = ssc + DIM;
    float* sbias = ssh + DIM;
    uint32_t sb = smem_u32(sm);
    int tid = threadIdx.x, wid = tid >> 5, lane = tid & 31;

    if (blockIdx.x == 0 && tid < DIM) {
        g_cs[0][tid] = 0.f;
        g_cq[0][tid] = 0.f;
    }
    if (tid < DIM) {
        float s0 = 0.f, s1 = 0.f, s2 = 0.f, s3 = 0.f;
        float q0 = 0.f, q1 = 0.f, q2 = 0.f, q3 = 0.f;
        for (int p = 0; p < 256; p += 4) {
            s0 += g_bn_ps[p][tid];     s1 += g_bn_ps[p + 1][tid];
            s2 += g_bn_ps[p + 2][tid]; s3 += g_bn_ps[p + 3][tid];
            q0 += g_bn_pq[p][tid];     q1 += g_bn_pq[p + 1][tid];
            q2 += g_bn_pq[p + 2][tid]; q3 += g_bn_pq[p + 3][tid];
        }
        float mu = ((s0 + s1) + (s2 + s3)) * n_inv;
        float var = ((q0 + q1) + (q2 + q3)) * n_inv - mu * mu;
        float s = gamma[tid] * rsqrtf(var + 1e-5f);
        ssc[tid] = s;
        ssh[tid] = beta[tid] - mu * s;
    }
    __syncthreads();

    int T = (n + 127) >> 7;
    int t = blockIdx.x;
    if (t >= T) return;

    stage_B_f32(sm, OFF_B1H, OFF_B1L, fin_w, ssc, tid);
    stage_B_f32(sm, OFF_B2H, OFF_B2L, W2, nullptr, tid);
    if (tid < DIM) {
        float acc = fin_b[tid];
        for (int d = 0; d < DIM; d++) acc += ssh[d] * fin_w[d * DIM + tid];
        sbias[tid] = acc;
    }

    {
        int row0 = t * 128;
        for (int g = tid; g < 4096; g += 512) {
            int r = g >> 5, c = (g & 31) * 4;
            int row = row0 + r;
            float4 av = make_float4(0.f, 0.f, 0.f, 0.f);
            if (row < n) av = *reinterpret_cast<const float4*>(&X[(size_t)row * DIM + c]);
            uint32_t eoff = (uint32_t)(r * PADK + c) * 2u;
            uint32_t al0, al1;
            uint32_t ah0 = pack_hi(av.x, av.y, al0);
            uint32_t ah1 = pack_hi(av.z, av.w, al1);
            *reinterpret_cast<uint2*>(sm + OFF_AH + eoff) = make_uint2(ah0, ah1);
            *reinterpret_cast<uint2*>(sm + OFF_AL + eoff) = make_uint2(al0, al1);
        }
    }
    __syncthreads();

    int wm = (wid & 3) * 32;
    int wn = (wid >> 2) * 32;

    while (true) {
        int tn = t + gridDim.x;
        bool hn = tn < T;
        float4 raw[8];
        if (hn) {
            int row0n = tn * 128;
#pragma unroll
            for (int q = 0; q < 8; q++) {
                int g = q * 512 + tid;
                int r = g >> 5, c = (g & 31) * 4;
                int row = row0n + r;
                raw[q] = (row < n)
                    ? *reinterpret_cast<const float4*>(&X[(size_t)row * DIM + c])
                    : make_float4(0.f, 0.f, 0.f, 0.f);
            }
        }

        float acc[2][4][4];
#pragma unroll
        for (int mg = 0; mg < 2; mg++)
#pragma unroll
            for (int ng = 0; ng < 4; ng++)
#pragma unroll
                for (int q = 0; q < 4; q++) acc[mg][ng][q] = 0.f;

        mma_mainloop(sb, OFF_B1H, OFF_B1L, wm, wn, lane, acc);
        __syncthreads();

        {
            int rl = wm + (lane >> 2);
            int cb = wn + (lane & 3) * 2;
#pragma unroll
            for (int mg = 0; mg < 2; mg++)
#pragma unroll
                for (int half = 0; half < 2; half++) {
                    int r = rl + mg * 16 + half * 8;
#pragma unroll
                    for (int ng = 0; ng < 4; ng++) {
                        int col = cb + ng * 8;
                        float v0 = acc[mg][ng][half * 2] + sbias[col];
                        float v1 = acc[mg][ng][half * 2 + 1] + sbias[col + 1];
                        uint32_t lo;
                        uint32_t hi = pack_hi(v0, v1, lo);
                        uint32_t eoff = (uint32_t)(r * PADK + col) * 2u;
                        *reinterpret_cast<uint32_t*>(sm + OFF_AH + eoff) = hi;
                        *reinterpret_cast<uint32_t*>(sm + OFF_AL + eoff) = lo;
                    }
                }
        }
        __syncthreads();

#pragma unroll
        for (int mg = 0; mg < 2; mg++)
#pragma unroll
            for (int ng = 0; ng < 4; ng++)
#pragma unroll
                for (int q = 0; q < 4; q++) acc[mg][ng][q] = 0.f;

        mma_mainloop(sb, OFF_B2H, OFF_B2L, wm, wn, lane, acc);

        int row0 = t * 128;
        int rbase = row0 + wm + (lane >> 2);
        int cbase = wn + (lane & 3) * 2;
#pragma unroll
        for (int mg = 0; mg < 2; mg++)
#pragma unroll
            for (int half = 0; half < 2; half++) {
                int row = rbase + mg * 16 + half * 8;
                if (row < n) {
#pragma unroll
                    for (int ng = 0; ng < 4; ng++) {
                        int col = cbase + ng * 8;
                        __half2 o = __floats2half2_rn(acc[mg][ng][half * 2],
                                                      acc[mg][ng][half * 2 + 1]);
                        *reinterpret_cast<__half2*>(&C[(size_t)row * DIM + col]) = o;
                    }
                }
            }

        if (!hn) break;
        __syncthreads();
        {
#pragma unroll
            for (int q = 0; q < 8; q++) {
                int g = q * 512 + tid;
                int r = g >> 5, c = (g & 31) * 4;
                float4 av = raw[q];
                uint32_t eoff = (uint32_t)(r * PADK + c) * 2u;
                uint32_t al0, al1;
                uint32_t ah0 = pack_hi(av.x, av.y, al0);
                uint32_t ah1 = pack_hi(av.z, av.w, al1);
                *reinterpret_cast<uint2*>(sm + OFF_AH + eoff) = make_uint2(ah0, ah1);
                *reinterpret_cast<uint2*>(sm + OFF_AL + eoff) = make_uint2(al0, al1);
            }
        }
        __syncthreads();
        t = tn;
    }
}

// ======================= input BN stats -> per-block partials ===============
__global__ __launch_bounds__(256) void col_stats_k(const float* __restrict__ x, int n) {
    __shared__ float red[256];
    __shared__ float redq[128];
    int tid = threadIdx.x;
    red[tid] = 0.f;
    if (tid < 128) redq[tid] = 0.f;
    int w = tid >> 5, lane = tid & 31, c = lane * 4;
    int gw = blockIdx.x * 8 + w;
    const int STR = 256 * 8;
    float4 s = make_float4(0.f, 0.f, 0.f, 0.f);
    float4 q = make_float4(0.f, 0.f, 0.f, 0.f);
    __syncthreads();
    for (int r0 = gw; r0 < n; r0 += STR * 4) {
#pragma unroll
        for (int u = 0; u < 4; u++) {
            int row = r0 + u * STR;
            if (row < n) {
                float4 v = *reinterpret_cast<const float4*>(&x[(size_t)row * DIM + c]);
                s.x += v.x; s.y += v.y; s.z += v.z; s.w += v.w;
                q.x += v.x * v.x; q.y += v.y * v.y; q.z += v.z * v.z; q.w += v.w * v.w;
            }
        }
    }
    atomicAdd(&red[c], s.x);     atomicAdd(&red[c + 1], s.y);
    atomicAdd(&red[c + 2], s.z); atomicAdd(&red[c + 3], s.w);
    atomicAdd(&redq[c], q.x);     atomicAdd(&redq[c + 1], q.y);
    atomicAdd(&redq[c + 2], q.z); atomicAdd(&redq[c + 3], q.w);
    __syncthreads();
    if (tid < 128) {
        g_bn_ps[blockIdx.x][tid] = red[tid];
        g_bn_pq[blockIdx.x][tid] = redq[tid];
    }
}

// ======================= CSR build ==========================================
__global__ void hist_k(const int* __restrict__ er, int e) {
    int i = blockIdx.x * blockDim.x + threadIdx.x;
    if (i < e) atomicAdd(&g_cnt[er[i]], 1);
}

__global__ __launch_bounds__(256) void scan1_k(int n) {
    __shared__ int red[256];
    int tid = threadIdx.x;
    int i = blockIdx.x * 256 + tid;
    red[tid] = (i < n) ? g_cnt[i] : 0;
    __syncthreads();
    for (int off = 128; off > 0; off >>= 1) {
        if (tid < off) red[tid] += red[tid + off];
        __syncthreads();
    }
    if (tid == 0) g_bsum[blockIdx.x] = red[0];
}

__global__ __launch_bounds__(256) void scan3_k(int n, int nblk) {
    __shared__ int bs[256];
    __shared__ int s[256];
    int tid = threadIdx.x;
    bs[tid] = (tid < nblk) ? g_bsum[tid] : 0;
    __syncthreads();
    for (int off = 1; off < 256; off <<= 1) {
        int t = (tid >= off) ? bs[tid - off] : 0;
        __syncthreads();
        bs[tid] += t;
        __syncthreads();
    }
    int bpref = (blockIdx.x == 0) ? 0 : bs[blockIdx.x - 1];
    if (blockIdx.x == 0 && tid == 0) g_rowptr[n] = bs[255];
    int i = blockIdx.x * 256 + tid;
    int v = (i < n) ? g_cnt[i] : 0;
    s[tid] = v;
    __syncthreads();
    for (int off = 1; off < 256; off <<= 1) {
        int t = (tid >= off) ? s[tid - off] : 0;
        __syncthreads();
        s[tid] += t;
        __syncthreads();
    }
    if (i < n) {
        int excl = s[tid] - v + bpref;
        g_rowptr[i] = excl;
        g_wcur[i] = excl;
        g_cnt[i] = 0;
    }
}

__global__ void scatter_k(const int* __restrict__ er, const int* __restrict__ ec,
                          const float* __restrict__ ev, int e) {
    int i = blockIdx.x * blockDim.x + threadIdx.x;
    if (i < e) {
        int r = er[i];
        int pos = atomicAdd(&g_wcur[r], 1);
        g_edge[pos] = make_int2(ec[i], __float_as_int(ev[i]));
    }
}

// ======================= SPMM (fp16 in/out) + fused PairNorm stats ==========
// 512 threads / 16 warps; warp owns 4 rows -> 64 rows per block.
__global__ __launch_bounds__(512) void spmm_k(
    const __half* __restrict__ g, const float* __restrict__ bias,
    __half* __restrict__ h, int n, int slot) {
    __shared__ float red[256];
    int tid = threadIdx.x;
    if (tid < 256) red[tid] = 0.f;
    int w = tid >> 5, lane = tid & 31;
    int gw = blockIdx.x * 16 + w;
    int c = lane * 4;
    float4 b4 = *reinterpret_cast<const float4*>(&bias[c]);
    float4 ssum = make_float4(0.f, 0.f, 0.f, 0.f);
    float4 ssq = make_float4(0.f, 0.f, 0.f, 0.f);
    __syncthreads();
#pragma unroll
    for (int rr = 0; rr < 4; rr++) {
        int row = gw * 4 + rr;
        if (row >= n) break;
        int s = g_rowptr[row];
        int e = g_rowptr[row + 1];
        float4 acc = make_float4(0.f, 0.f, 0.f, 0.f);
        int i = s;
        for (; i + 7 < e; i += 8) {
            uint2 p[8];
            float vv[8];
#pragma unroll
            for (int u = 0; u < 8; u++) {
                int2 ed = g_edge[i + u];
                vv[u] = __int_as_float(ed.y);
                p[u] = *reinterpret_cast<const uint2*>(&g[(size_t)ed.x * DIM + c]);
            }
#pragma unroll
            for (int u = 0; u < 8; u++) {
                float4 gv = h4_to_f4(p[u]);
                acc.x += vv[u] * gv.x;
                acc.y += vv[u] * gv.y;
                acc.z += vv[u] * gv.z;
                acc.w += vv[u] * gv.w;
            }
        }
        if (i + 3 < e) {
            uint2 p[4];
            float vv[4];
#pragma unroll
            for (int u = 0; u < 4; u++) {
                int2 ed = g_edge[i + u];
                vv[u] = __int_as_float(ed.y);
                p[u] = *reinterpret_cast<const uint2*>(&g[(size_t)ed.x * DIM + c]);
            }
#pragma unroll
            for (int u = 0; u < 4; u++) {
                float4 gv = h4_to_f4(p[u]);
                acc.x += vv[u] * gv.x;
                acc.y += vv[u] * gv.y;
                acc.z += vv[u] * gv.z;
                acc.w += vv[u] * gv.w;
            }
            i += 4;
        }
        for (; i < e; i++) {
            int2 ed = g_edge[i];
            float v0 = __int_as_float(ed.y);
            float4 gv = h4_to_f4(*reinterpret_cast<const uint2*>(&g[(size_t)ed.x * DIM + c]));
            acc.x += v0 * gv.x; acc.y += v0 * gv.y;
            acc.z += v0 * gv.z; acc.w += v0 * gv.w;
        }
        acc.x += b4.x; acc.y += b4.y; acc.z += b4.z; acc.w += b4.w;
        __half2 o0 = __floats2half2_rn(acc.x, acc.y);
        __half2 o1 = __floats2half2_rn(acc.z, acc.w);
        uint2 ov;
        ov.x = *reinterpret_cast<uint32_t*>(&o0);
        ov.y = *reinterpret_cast<uint32_t*>(&o1);
        *reinterpret_cast<uint2*>(&h[(size_t)row * DIM + c]) = ov;
        ssum.x += acc.x; ssum.y += acc.y; ssum.z += acc.z; ssum.w += acc.w;
        ssq.x += acc.x * acc.x; ssq.y += acc.y * acc.y;
        ssq.z += acc.z * acc.z; ssq.w += acc.w * acc.w;
    }
    atomicAdd(&red[c], ssum.x);     atomicAdd(&red[c + 1], ssum.y);
    atomicAdd(&red[c + 2], ssum.z); atomicAdd(&red[c + 3], ssum.w);
    atomicAdd(&red[128 + c], ssq.x);     atomicAdd(&red[128 + c + 1], ssq.y);
    atomicAdd(&red[128 + c + 2], ssq.z); atomicAdd(&red[128 + c + 3], ssq.w);
    __syncthreads();
    if (tid < 128) atomicAdd(&g_cs[slot][tid], red[tid]);
    else if (tid < 256) atomicAdd(&g_cq[slot][tid - 128], red[tid]);
}

// ======================= output GEMM + fused final PairNorm =================
__global__ __launch_bounds__(256) void gemm_out_k(
    const __half* __restrict__ H, const float* __restrict__ Xold,
    const float* __restrict__ W, const float* __restrict__ b,
    float* __restrict__ out, int n, int pn_slot, float n_inv) {
    __shared__ float sx[32 * DIM];
    __shared__ float sw[DIM * CDIM];
    __shared__ float smu[DIM];
    __shared__ float red[DIM];
    int tid = threadIdx.x;
    int row0 = blockIdx.x * 32;
    for (int i = tid; i < DIM * CDIM; i += 256) sw[i] = W[i];
    if (tid < DIM) {
        float mu = g_cs[pn_slot][tid] * n_inv;
        smu[tid] = mu;
        red[tid] = g_cq[pn_slot][tid] * n_inv - mu * mu;
    }
    __syncthreads();
    for (int off = 64; off > 0; off >>= 1) {
        if (tid < off) red[tid] += red[tid + off];
        __syncthreads();
    }
    if (tid == 0) red[0] = rsqrtf(1e-6f + red[0]);
    __syncthreads();
    float s = red[0];
#pragma unroll
    for (int q = 0; q < 4; q++) {
        int flat = (q * 256 + tid) * 4;
        int r = flat >> 7, c = flat & 127;
        int row = row0 + r;
        float4 v = make_float4(0.f, 0.f, 0.f, 0.f);
        if (row < n) {
            float4 hv = h4_to_f4(*reinterpret_cast<const uint2*>(&H[(size_t)row * DIM + c]));
            float4 m = *reinterpret_cast<const float4*>(&smu[c]);
            float4 xo = *reinterpret_cast<const float4*>(&Xold[(size_t)row * DIM + c]);
            v.x = fmaxf((hv.x - m.x) * s, 0.f) + xo.x;
            v.y = fmaxf((hv.y - m.y) * s, 0.f) + xo.y;
            v.z = fmaxf((hv.z - m.z) * s, 0.f) + xo.z;
            v.w = fmaxf((hv.w - m.w) * s, 0.f) + xo.w;
        }
        *reinterpret_cast<float4*>(&sx[flat]) = v;
    }
    __syncthreads();
    int r = tid >> 3;
    int c0 = (tid & 7) * 5;
    float acc[5];
#pragma unroll
    for (int j = 0; j < 5; j++) acc[j] = b[c0 + j];
#pragma unroll 4
    for (int k = 0; k < DIM; k++) {
        float xv = sx[r * DIM + k];
#pragma unroll
        for (int j = 0; j < 5; j++) acc[j] += xv * sw[k * CDIM + c0 + j];
    }
    if (row0 + r < n) {
#pragma unroll
        for (int j = 0; j < 5; j++) out[(size_t)(row0 + r) * CDIM + c0 + j] = acc[j];
    }
}

// ======================= launch =============================================
extern "C" void kernel_launch(void* const* d_in, const int* in_sizes, int n_in,
                              void* d_out, int out_size) {
    const float* x      = (const float*)d_in[0];
    const int*   er     = (const int*)d_in[1];
    const int*   ec     = (const int*)d_in[2];
    const float* ev     = (const float*)d_in[3];
    const float* gamma  = (const float*)d_in[4];
    const float* beta   = (const float*)d_in[5];
    const float* fin_w  = (const float*)d_in[6];
    const float* fin_b  = (const float*)d_in[7];
    const float* gc_w   = (const float*)d_in[8];
    const float* gc_b   = (const float*)d_in[9];
    const float* fout_w = (const float*)d_in[10];
    const float* fout_b = (const float*)d_in[11];
    float* out = (float*)d_out;

    int n = in_sizes[0] / DIM;
    int e = in_sizes[1];
    float n_inv = 1.0f / (float)n;

    float* xbuf;
    __half *g16, *h16;
    cudaGetSymbolAddress((void**)&xbuf, g_xbuf);
    cudaGetSymbolAddress((void**)&g16, g_g16);
    cudaGetSymbolAddress((void**)&h16, g_h16);

    static cudaStream_t s2 = nullptr;
    static cudaEvent_t evFork = nullptr, evJoin = nullptr;
    if (s2 == nullptr) {
        cudaStreamCreateWithFlags(&s2, cudaStreamNonBlocking);
        cudaEventCreateWithFlags(&evFork, cudaEventDisableTiming);
        cudaEventCreateWithFlags(&evJoin, cudaEventDisableTiming);
        cudaFuncSetAttribute(gemm_mma_k, cudaFuncAttributeMaxDynamicSharedMemorySize, GEMM_SMEM_BYTES);
        cudaFuncSetAttribute(gemm_fused_k, cudaFuncAttributeMaxDynamicSharedMemorySize, FUSED_SMEM_BYTES);
    }

    int spblocks = (n + 63) / 64;    // spmm: 16 warps x 4 rows per block
    int oblocks = (n + 31) / 32;     // gemm_out: 32 rows per block
    int nblk = (n + 255) / 256;
    int eblk = (e + 255) / 256;
    const int WMAT = DIM * DIM;

    // ---- fork: branch B (BN stats -> fused GEMM @128 blocks) concurrent
    //      with CSR build; 20 SMs left free so CSR genuinely overlaps.
    cudaEventRecord(evFork, 0);
    cudaStreamWaitEvent(s2, evFork, 0);

    // branch B (stream s2)
    col_stats_k<<<256, 256, 0, s2>>>(x, n);
    gemm_fused_k<<<128, 512, FUSED_SMEM_BYTES, s2>>>(
        x, fin_w, fin_b, gamma, beta, gc_w, g16, n, n_inv);

    // main stream: CSR build
    hist_k<<<eblk, 256>>>(er, e);
    scan1_k<<<nblk, 256>>>(n);
    scan3_k<<<nblk, 256>>>(n, nblk);
    scatter_k<<<eblk, 256>>>(er, ec, ev, e);

    // ---- join
    cudaEventRecord(evJoin, s2);
    cudaStreamWaitEvent(0, evJoin, 0);

    // ---- layer 0 spmm ----
    spmm_k<<<spblocks, 512>>>(g16, gc_b + 0 * DIM, h16, n, 0);

    // ---- layers 1..3: persistent GEMM with fused PairNorm-apply on A ----
    for (int i = 1; i < NLAYER; i++) {
        gemm_mma_k<<<NSM, 512, GEMM_SMEM_BYTES>>>(
            h16, xbuf, xbuf, gc_w + i * WMAT,
            g16, n, (i - 1) & 1, i & 1, (i >= 2) ? 1 : 0, n_inv);
        spmm_k<<<spblocks, 512>>>(g16, gc_b + i * DIM, h16, n, i & 1);
    }

    // ---- output projection with fused final PairNorm (slot 1, addold) ----
    gemm_out_k<<<oblocks, 256>>>(h16, xbuf, fout_w, fout_b, out, n, (NLAYER - 1) & 1, n_inv);
}

// round 15
// speedup vs baseline: 1.3188x; 1.0614x over previous
#include <cuda_runtime.h>
#include <cuda_bf16.h>
#include <cuda_fp16.h>
#include <cstdint>

#define DIM 128
#define CDIM 40
#define NLAYER 4
#define NMAX 50000
#define EMAX 800000
#define NSM 148

// ---------------- device scratch (static: no allocations allowed) ----------
__device__ float  g_xbuf[NMAX * DIM];     // fp32 residual
__device__ __half g_g16[NMAX * DIM];      // fp16 gather buffer (GEMM -> spmm)
__device__ __half g_h16[NMAX * DIM];      // fp16 spmm output (spmm -> GEMM)
__device__ float g_cs[2][DIM];            // PairNorm column sums (parity slots)
__device__ float g_cq[2][DIM];            // PairNorm column sumsq
__device__ float g_bn_ps[256][DIM];       // BN stats partials (no zero needed)
__device__ float g_bn_pq[256][DIM];
__device__ int   g_rowptr[NMAX + 1];
__device__ int   g_cnt[NMAX];             // invariant: zero between replays
__device__ int   g_wcur[NMAX];
__device__ int   g_bsum[256];
__device__ int2  g_edge[EMAX];            // (colidx, val-bits) packed

// ======================= helpers ===========================================
__device__ __forceinline__ uint32_t smem_u32(const void* p) {
    uint32_t a;
    asm("{ .reg .u64 t; cvta.to.shared.u64 t, %1; cvt.u32.u64 %0, t; }" : "=r"(a) : "l"(p));
    return a;
}
__device__ __forceinline__ void ldm_x4(uint32_t* r, uint32_t addr) {
    asm volatile("ldmatrix.sync.aligned.m8n8.x4.shared.b16 {%0,%1,%2,%3}, [%4];"
                 : "=r"(r[0]), "=r"(r[1]), "=r"(r[2]), "=r"(r[3]) : "r"(addr));
}
__device__ __forceinline__ void ldm_x4_t(uint32_t* r, uint32_t addr) {
    asm volatile("ldmatrix.sync.aligned.m8n8.x4.trans.shared.b16 {%0,%1,%2,%3}, [%4];"
                 : "=r"(r[0]), "=r"(r[1]), "=r"(r[2]), "=r"(r[3]) : "r"(addr));
}
__device__ __forceinline__ void mma_bf16(float* c, const uint32_t* a, const uint32_t* b) {
    asm volatile(
        "mma.sync.aligned.m16n8k16.row.col.f32.bf16.bf16.f32 "
        "{%0,%1,%2,%3}, {%4,%5,%6,%7}, {%8,%9}, {%0,%1,%2,%3};"
        : "+f"(c[0]), "+f"(c[1]), "+f"(c[2]), "+f"(c[3])
        : "r"(a[0]), "r"(a[1]), "r"(a[2]), "r"(a[3]), "r"(b[0]), "r"(b[1]));
}
__device__ __forceinline__ uint32_t pack_hi(float x, float y, uint32_t& lo) {
    __nv_bfloat16 hx = __float2bfloat16(x);
    __nv_bfloat16 hy = __float2bfloat16(y);
    __nv_bfloat16 lx = __float2bfloat16(x - __bfloat162float(hx));
    __nv_bfloat16 ly = __float2bfloat16(y - __bfloat162float(hy));
    lo = (uint32_t)__bfloat16_as_ushort(lx) | ((uint32_t)__bfloat16_as_ushort(ly) << 16);
    return (uint32_t)__bfloat16_as_ushort(hx) | ((uint32_t)__bfloat16_as_ushort(hy) << 16);
}
__device__ __forceinline__ float4 h4_to_f4(uint2 hv) {
    float2 lo = __half22float2(*reinterpret_cast<__half2*>(&hv.x));
    float2 hi = __half22float2(*reinterpret_cast<__half2*>(&hv.y));
    return make_float4(lo.x, lo.y, hi.x, hi.y);
}

// ======================= GEMM common pieces =================================
#define PADK 136
#define TILE_B (128 * PADK * 2)
#define OFF_AH 0
#define OFF_AL TILE_B
#define OFF_B1H (2 * TILE_B)
#define OFF_B1L (3 * TILE_B)
#define OFF_B2H (4 * TILE_B)
#define OFF_B2L (5 * TILE_B)
#define GEMM_SMEM_BYTES  (4 * TILE_B + 2048)
#define FUSED_SMEM_BYTES (6 * TILE_B + 2048)

__device__ __forceinline__ void mma_mainloop(uint32_t sb, int bOffH, int bOffL,
                                             int wm, int wn, int lane,
                                             float acc[2][4][4]) {
    int lrow = lane & 15;
    int lcol8 = (lane >> 4) << 3;
#pragma unroll
    for (int t = 0; t < 3; t++) {
        uint32_t aBase = sb + ((t == 2) ? OFF_AL : OFF_AH);
        uint32_t bBase = sb + ((t == 1) ? bOffL : bOffH);
#pragma unroll
        for (int k0 = 0; k0 < 128; k0 += 16) {
            uint32_t a[2][4];
#pragma unroll
            for (int mg = 0; mg < 2; mg++)
                ldm_x4(a[mg], aBase + (uint32_t)((wm + mg * 16 + lrow) * PADK + k0 + lcol8) * 2u);
            uint32_t b[2][4];
#pragma unroll
            for (int nc = 0; nc < 2; nc++)
                ldm_x4_t(b[nc], bBase + (uint32_t)((k0 + lrow) * PADK + wn + nc * 16 + lcol8) * 2u);
#pragma unroll
            for (int mg = 0; mg < 2; mg++)
#pragma unroll
                for (int ng = 0; ng < 4; ng++)
                    mma_bf16(acc[mg][ng], a[mg], &b[ng >> 1][(ng & 1) * 2]);
        }
    }
}

__device__ __forceinline__ void stage_B_f32(char* sm, int offH, int offL,
                                            const float* __restrict__ W,
                                            const float* rscale, int tid) {
    for (int g = tid; g < 4096; g += 512) {
        int r = g >> 5, c = (g & 31) * 4;
        float4 w = *reinterpret_cast<const float4*>(&W[r * DIM + c]);
        if (rscale) {
            float s = rscale[r];
            w.x *= s; w.y *= s; w.z *= s; w.w *= s;
        }
        uint32_t eoff = (uint32_t)(r * PADK + c) * 2u;
        uint32_t l0, l1;
        uint32_t h0 = pack_hi(w.x, w.y, l0);
        uint32_t h1 = pack_hi(w.z, w.w, l1);
        *reinterpret_cast<uint2*>(sm + offH + eoff) = make_uint2(h0, h1);
        *reinterpret_cast<uint2*>(sm + offL + eoff) = make_uint2(l0, l1);
    }
}

// ======================= main GEMM (persistent, fused PairNorm on A) ========
__global__ __launch_bounds__(512) void gemm_mma_k(
    const __half* __restrict__ A, const float* __restrict__ Xold,
    float* __restrict__ Xwrite, const float* __restrict__ Wf32,
    __half* __restrict__ C, int n,
    int pn_slot, int zero_slot, int addold, float n_inv) {
    extern __shared__ char sm[];
    float* smu = reinterpret_cast<float*>(sm + 4 * TILE_B);
    float* red = smu + DIM;
    uint32_t sb = smem_u32(sm);
    int tid = threadIdx.x, wid = tid >> 5, lane = tid & 31;

    if (zero_slot >= 0 && blockIdx.x == 0 && tid < DIM) {
        g_cs[zero_slot][tid] = 0.f;
        g_cq[zero_slot][tid] = 0.f;
    }

    if (tid < DIM) {
        float mu = g_cs[pn_slot][tid] * n_inv;
        smu[tid] = mu;
        red[tid] = g_cq[pn_slot][tid] * n_inv - mu * mu;
    }
    __syncthreads();
    for (int off = 64; off > 0; off >>= 1) {
        if (tid < off) red[tid] += red[tid + off];
        __syncthreads();
    }
    if (tid == 0) red[0] = rsqrtf(1e-6f + red[0]);
    __syncthreads();
    float pscale = red[0];

    int T = (n + 127) >> 7;
    int t = blockIdx.x;
    if (t >= T) return;

    stage_B_f32(sm, OFF_B1H, OFF_B1L, Wf32, nullptr, tid);

    {
        int row0 = t * 128;
        for (int g = tid; g < 4096; g += 512) {
            int r = g >> 5, c = (g & 31) * 4;
            int row = row0 + r;
            float4 av = make_float4(0.f, 0.f, 0.f, 0.f);
            if (row < n) {
                av = h4_to_f4(*reinterpret_cast<const uint2*>(&A[(size_t)row * DIM + c]));
                float4 m = *reinterpret_cast<const float4*>(&smu[c]);
                av.x = fmaxf((av.x - m.x) * pscale, 0.f);
                av.y = fmaxf((av.y - m.y) * pscale, 0.f);
                av.z = fmaxf((av.z - m.z) * pscale, 0.f);
                av.w = fmaxf((av.w - m.w) * pscale, 0.f);
                if (addold) {
                    float4 xo = *reinterpret_cast<const float4*>(&Xold[(size_t)row * DIM + c]);
                    av.x += xo.x; av.y += xo.y; av.z += xo.z; av.w += xo.w;
                }
                *reinterpret_cast<float4*>(&Xwrite[(size_t)row * DIM + c]) = av;
            }
            uint32_t eoff = (uint32_t)(r * PADK + c) * 2u;
            uint32_t al0, al1;
            uint32_t ah0 = pack_hi(av.x, av.y, al0);
            uint32_t ah1 = pack_hi(av.z, av.w, al1);
            *reinterpret_cast<uint2*>(sm + OFF_AH + eoff) = make_uint2(ah0, ah1);
            *reinterpret_cast<uint2*>(sm + OFF_AL + eoff) = make_uint2(al0, al1);
        }
    }
    __syncthreads();

    int wm = (wid & 3) * 32;
    int wn = (wid >> 2) * 32;

    while (true) {
        int tn = t + gridDim.x;
        bool hn = tn < T;
        uint2 raw[8];
        if (hn) {
            int row0n = tn * 128;
#pragma unroll
            for (int q = 0; q < 8; q++) {
                int g = q * 512 + tid;
                int r = g >> 5, c = (g & 31) * 4;
                int row = row0n + r;
                raw[q] = (row < n)
                    ? *reinterpret_cast<const uint2*>(&A[(size_t)row * DIM + c])
                    : make_uint2(0u, 0u);
            }
        }

        float acc[2][4][4];
#pragma unroll
        for (int mg = 0; mg < 2; mg++)
#pragma unroll
            for (int ng = 0; ng < 4; ng++)
#pragma unroll
                for (int q = 0; q < 4; q++) acc[mg][ng][q] = 0.f;

        mma_mainloop(sb, OFF_B1H, OFF_B1L, wm, wn, lane, acc);

        int row0 = t * 128;
        int rbase = row0 + wm + (lane >> 2);
        int cbase = wn + (lane & 3) * 2;
#pragma unroll
        for (int mg = 0; mg < 2; mg++)
#pragma unroll
            for (int half = 0; half < 2; half++) {
                int row = rbase + mg * 16 + half * 8;
                if (row < n) {
#pragma unroll
                    for (int ng = 0; ng < 4; ng++) {
                        int col = cbase + ng * 8;
                        __half2 o = __floats2half2_rn(acc[mg][ng][half * 2],
                                                      acc[mg][ng][half * 2 + 1]);
                        *reinterpret_cast<__half2*>(&C[(size_t)row * DIM + col]) = o;
                    }
                }
            }

        if (!hn) break;
        __syncthreads();
        {
            int row0n = tn * 128;
#pragma unroll
            for (int q = 0; q < 8; q++) {
                int g = q * 512 + tid;
                int r = g >> 5, c = (g & 31) * 4;
                int row = row0n + r;
                float4 av = make_float4(0.f, 0.f, 0.f, 0.f);
                if (row < n) {
                    av = h4_to_f4(raw[q]);
                    float4 m = *reinterpret_cast<const float4*>(&smu[c]);
                    av.x = fmaxf((av.x - m.x) * pscale, 0.f);
                    av.y = fmaxf((av.y - m.y) * pscale, 0.f);
                    av.z = fmaxf((av.z - m.z) * pscale, 0.f);
                    av.w = fmaxf((av.w - m.w) * pscale, 0.f);
                    if (addold) {
                        float4 xo = *reinterpret_cast<const float4*>(&Xold[(size_t)row * DIM + c]);
                        av.x += xo.x; av.y += xo.y; av.z += xo.z; av.w += xo.w;
                    }
                    *reinterpret_cast<float4*>(&Xwrite[(size_t)row * DIM + c]) = av;
                }
                uint32_t eoff = (uint32_t)(r * PADK + c) * 2u;
                uint32_t al0, al1;
                uint32_t ah0 = pack_hi(av.x, av.y, al0);
                uint32_t ah1 = pack_hi(av.z, av.w, al1);
                *reinterpret_cast<uint2*>(sm + OFF_AH + eoff) = make_uint2(ah0, ah1);
                *reinterpret_cast<uint2*>(sm + OFF_AL + eoff) = make_uint2(al0, al1);
            }
        }
        __syncthreads();
        t = tn;
    }
}

// ======================= fused fc_in + layer-0 GEMM (persistent) ============
__global__ __launch_bounds__(512) void gemm_fused_k(
    const float* __restrict__ X,
    const float* __restrict__ fin_w, const float* __restrict__ fin_b,
    const float* __restrict__ gamma, const float* __restrict__ beta,
    const float* __restrict__ W2,
    __half* __restrict__ C, int n, float n_inv) {
    extern __shared__ char sm[];
    float* ssc = reinterpret_cast<float*>(sm + 6 * TILE_B);
    float* ssh = ssc + DIM;
    float* sbias = ssh + DIM;
    uint32_t sb = smem_u32(sm);
    int tid = threadIdx.x, wid = tid >> 5, lane = tid & 31;

    if (blockIdx.x == 0 && tid < DIM) {
        g_cs[0][tid] = 0.f;
        g_cq[0][tid] = 0.f;
    }
    if (tid < DIM) {
        float s0 = 0.f, s1 = 0.f, s2 = 0.f, s3 = 0.f;
        float q0 = 0.f, q1 = 0.f, q2 = 0.f, q3 = 0.f;
        for (int p = 0; p < 256; p += 4) {
            s0 += g_bn_ps[p][tid];     s1 += g_bn_ps[p + 1][tid];
            s2 += g_bn_ps[p + 2][tid]; s3 += g_bn_ps[p + 3][tid];
            q0 += g_bn_pq[p][tid];     q1 += g_bn_pq[p + 1][tid];
            q2 += g_bn_pq[p + 2][tid]; q3 += g_bn_pq[p + 3][tid];
        }
        float mu = ((s0 + s1) + (s2 + s3)) * n_inv;
        float var = ((q0 + q1) + (q2 + q3)) * n_inv - mu * mu;
        float s = gamma[tid] * rsqrtf(var + 1e-5f);
        ssc[tid] = s;
        ssh[tid] = beta[tid] - mu * s;
    }
    __syncthreads();

    int T = (n + 127) >> 7;
    int t = blockIdx.x;
    if (t >= T) return;

    stage_B_f32(sm, OFF_B1H, OFF_B1L, fin_w, ssc, tid);
    stage_B_f32(sm, OFF_B2H, OFF_B2L, W2, nullptr, tid);
    if (tid < DIM) {
        float acc = fin_b[tid];
        for (int d = 0; d < DIM; d++) acc += ssh[d] * fin_w[d * DIM + tid];
        sbias[tid] = acc;
    }

    {
        int row0 = t * 128;
        for (int g = tid; g < 4096; g += 512) {
            int r = g >> 5, c = (g & 31) * 4;
            int row = row0 + r;
            float4 av = make_float4(0.f, 0.f, 0.f, 0.f);
            if (row < n) av = *reinterpret_cast<const float4*>(&X[(size_t)row * DIM + c]);
            uint32_t eoff = (uint32_t)(r * PADK + c) * 2u;
            uint32_t al0, al1;
            uint32_t ah0 = pack_hi(av.x, av.y, al0);
            uint32_t ah1 = pack_hi(av.z, av.w, al1);
            *reinterpret_cast<uint2*>(sm + OFF_AH + eoff) = make_uint2(ah0, ah1);
            *reinterpret_cast<uint2*>(sm + OFF_AL + eoff) = make_uint2(al0, al1);
        }
    }
    __syncthreads();

    int wm = (wid & 3) * 32;
    int wn = (wid >> 2) * 32;

    while (true) {
        int tn = t + gridDim.x;
        bool hn = tn < T;
        float4 raw[8];
        if (hn) {
            int row0n = tn * 128;
#pragma unroll
            for (int q = 0; q < 8; q++) {
                int g = q * 512 + tid;
                int r = g >> 5, c = (g & 31) * 4;
                int row = row0n + r;
                raw[q] = (row < n)
                    ? *reinterpret_cast<const float4*>(&X[(size_t)row * DIM + c])
                    : make_float4(0.f, 0.f, 0.f, 0.f);
            }
        }

        float acc[2][4][4];
#pragma unroll
        for (int mg = 0; mg < 2; mg++)
#pragma unroll
            for (int ng = 0; ng < 4; ng++)
#pragma unroll
                for (int q = 0; q < 4; q++) acc[mg][ng][q] = 0.f;

        mma_mainloop(sb, OFF_B1H, OFF_B1L, wm, wn, lane, acc);
        __syncthreads();

        {
            int rl = wm + (lane >> 2);
            int cb = wn + (lane & 3) * 2;
#pragma unroll
            for (int mg = 0; mg < 2; mg++)
#pragma unroll
                for (int half = 0; half < 2; half++) {
                    int r = rl + mg * 16 + half * 8;
#pragma unroll
                    for (int ng = 0; ng < 4; ng++) {
                        int col = cb + ng * 8;
                        float v0 = acc[mg][ng][half * 2] + sbias[col];
                        float v1 = acc[mg][ng][half * 2 + 1] + sbias[col + 1];
                        uint32_t lo;
                        uint32_t hi = pack_hi(v0, v1, lo);
                        uint32_t eoff = (uint32_t)(r * PADK + col) * 2u;
                        *reinterpret_cast<uint32_t*>(sm + OFF_AH + eoff) = hi;
                        *reinterpret_cast<uint32_t*>(sm + OFF_AL + eoff) = lo;
                    }
                }
        }
        __syncthreads();

#pragma unroll
        for (int mg = 0; mg < 2; mg++)
#pragma unroll
            for (int ng = 0; ng < 4; ng++)
#pragma unroll
                for (int q = 0; q < 4; q++) acc[mg][ng][q] = 0.f;

        mma_mainloop(sb, OFF_B2H, OFF_B2L, wm, wn, lane, acc);

        int row0 = t * 128;
        int rbase = row0 + wm + (lane >> 2);
        int cbase = wn + (lane & 3) * 2;
#pragma unroll
        for (int mg = 0; mg < 2; mg++)
#pragma unroll
            for (int half = 0; half < 2; half++) {
                int row = rbase + mg * 16 + half * 8;
                if (row < n) {
#pragma unroll
                    for (int ng = 0; ng < 4; ng++) {
                        int col = cbase + ng * 8;
                        __half2 o = __floats2half2_rn(acc[mg][ng][half * 2],
                                                      acc[mg][ng][half * 2 + 1]);
                        *reinterpret_cast<__half2*>(&C[(size_t)row * DIM + col]) = o;
                    }
                }
            }

        if (!hn) break;
        __syncthreads();
        {
#pragma unroll
            for (int q = 0; q < 8; q++) {
                int g = q * 512 + tid;
                int r = g >> 5, c = (g & 31) * 4;
                float4 av = raw[q];
                uint32_t eoff = (uint32_t)(r * PADK + c) * 2u;
                uint32_t al0, al1;
                uint32_t ah0 = pack_hi(av.x, av.y, al0);
                uint32_t ah1 = pack_hi(av.z, av.w, al1);
                *reinterpret_cast<uint2*>(sm + OFF_AH + eoff) = make_uint2(ah0, ah1);
                *reinterpret_cast<uint2*>(sm + OFF_AL + eoff) = make_uint2(al0, al1);
            }
        }
        __syncthreads();
        t = tn;
    }
}

// ======================= input BN stats -> per-block partials ===============
__global__ __launch_bounds__(256) void col_stats_k(const float* __restrict__ x, int n) {
    __shared__ float red[256];
    __shared__ float redq[128];
    int tid = threadIdx.x;
    red[tid] = 0.f;
    if (tid < 128) redq[tid] = 0.f;
    int w = tid >> 5, lane = tid & 31, c = lane * 4;
    int gw = blockIdx.x * 8 + w;
    const int STR = 256 * 8;
    float4 s = make_float4(0.f, 0.f, 0.f, 0.f);
    float4 q = make_float4(0.f, 0.f, 0.f, 0.f);
    __syncthreads();
    for (int r0 = gw; r0 < n; r0 += STR * 4) {
#pragma unroll
        for (int u = 0; u < 4; u++) {
            int row = r0 + u * STR;
            if (row < n) {
                float4 v = *reinterpret_cast<const float4*>(&x[(size_t)row * DIM + c]);
                s.x += v.x; s.y += v.y; s.z += v.z; s.w += v.w;
                q.x += v.x * v.x; q.y += v.y * v.y; q.z += v.z * v.z; q.w += v.w * v.w;
            }
        }
    }
    atomicAdd(&red[c], s.x);     atomicAdd(&red[c + 1], s.y);
    atomicAdd(&red[c + 2], s.z); atomicAdd(&red[c + 3], s.w);
    atomicAdd(&redq[c], q.x);     atomicAdd(&redq[c + 1], q.y);
    atomicAdd(&redq[c + 2], q.z); atomicAdd(&redq[c + 3], q.w);
    __syncthreads();
    if (tid < 128) {
        g_bn_ps[blockIdx.x][tid] = red[tid];
        g_bn_pq[blockIdx.x][tid] = redq[tid];
    }
}

// ======================= CSR build ==========================================
__global__ void hist_k(const int* __restrict__ er, int e) {
    int i = blockIdx.x * blockDim.x + threadIdx.x;
    if (i < e) atomicAdd(&g_cnt[er[i]], 1);
}

__global__ __launch_bounds__(256) void scan1_k(int n) {
    __shared__ int red[256];
    int tid = threadIdx.x;
    int i = blockIdx.x * 256 + tid;
    red[tid] = (i < n) ? g_cnt[i] : 0;
    __syncthreads();
    for (int off = 128; off > 0; off >>= 1) {
        if (tid < off) red[tid] += red[tid + off];
        __syncthreads();
    }
    if (tid == 0) g_bsum[blockIdx.x] = red[0];
}

__global__ __launch_bounds__(256) void scan3_k(int n, int nblk) {
    __shared__ int bs[256];
    __shared__ int s[256];
    int tid = threadIdx.x;
    bs[tid] = (tid < nblk) ? g_bsum[tid] : 0;
    __syncthreads();
    for (int off = 1; off < 256; off <<= 1) {
        int t = (tid >= off) ? bs[tid - off] : 0;
        __syncthreads();
        bs[tid] += t;
        __syncthreads();
    }
    int bpref = (blockIdx.x == 0) ? 0 : bs[blockIdx.x - 1];
    if (blockIdx.x == 0 && tid == 0) g_rowptr[n] = bs[255];
    int i = blockIdx.x * 256 + tid;
    int v = (i < n) ? g_cnt[i] : 0;
    s[tid] = v;
    __syncthreads();
    for (int off = 1; off < 256; off <<= 1) {
        int t = (tid >= off) ? s[tid - off] : 0;
        __syncthreads();
        s[tid] += t;
        __syncthreads();
    }
    if (i < n) {
        int excl = s[tid] - v + bpref;
        g_rowptr[i] = excl;
        g_wcur[i] = excl;
        g_cnt[i] = 0;
    }
}

__global__ void scatter_k(const int* __restrict__ er, const int* __restrict__ ec,
                          const float* __restrict__ ev, int e) {
    int i = blockIdx.x * blockDim.x + threadIdx.x;
    if (i < e) {
        int r = er[i];
        int pos = atomicAdd(&g_wcur[r], 1);
        g_edge[pos] = make_int2(ec[i], __float_as_int(ev[i]));
    }
}

// ======================= SPMM (fp16 in/out) + fused PairNorm stats ==========
// 256 threads / 8 warps; warp owns 4 rows -> 32 rows per block (R11 config).
__global__ __launch_bounds__(256) void spmm_k(
    const __half* __restrict__ g, const float* __restrict__ bias,
    __half* __restrict__ h, int n, int slot) {
    __shared__ float red[256];
    int tid = threadIdx.x;
    red[tid] = 0.f;
    int w = tid >> 5, lane = tid & 31;
    int gw = blockIdx.x * 8 + w;
    int c = lane * 4;
    float4 b4 = *reinterpret_cast<const float4*>(&bias[c]);
    float4 ssum = make_float4(0.f, 0.f, 0.f, 0.f);
    float4 ssq = make_float4(0.f, 0.f, 0.f, 0.f);
    __syncthreads();
#pragma unroll
    for (int rr = 0; rr < 4; rr++) {
        int row = gw * 4 + rr;
        if (row >= n) break;
        int s = g_rowptr[row];
        int e = g_rowptr[row + 1];
        float4 acc = make_float4(0.f, 0.f, 0.f, 0.f);
        int i = s;
        for (; i + 7 < e; i += 8) {
            uint2 p[8];
            float vv[8];
#pragma unroll
            for (int u = 0; u < 8; u++) {
                int2 ed = g_edge[i + u];
                vv[u] = __int_as_float(ed.y);
                p[u] = *reinterpret_cast<const uint2*>(&g[(size_t)ed.x * DIM + c]);
            }
#pragma unroll
            for (int u = 0; u < 8; u++) {
                float4 gv = h4_to_f4(p[u]);
                acc.x += vv[u] * gv.x;
                acc.y += vv[u] * gv.y;
                acc.z += vv[u] * gv.z;
                acc.w += vv[u] * gv.w;
            }
        }
        if (i + 3 < e) {
            uint2 p[4];
            float vv[4];
#pragma unroll
            for (int u = 0; u < 4; u++) {
                int2 ed = g_edge[i + u];
                vv[u] = __int_as_float(ed.y);
                p[u] = *reinterpret_cast<const uint2*>(&g[(size_t)ed.x * DIM + c]);
            }
#pragma unroll
            for (int u = 0; u < 4; u++) {
                float4 gv = h4_to_f4(p[u]);
                acc.x += vv[u] * gv.x;
                acc.y += vv[u] * gv.y;
                acc.z += vv[u] * gv.z;
                acc.w += vv[u] * gv.w;
            }
            i += 4;
        }
        for (; i < e; i++) {
            int2 ed = g_edge[i];
            float v0 = __int_as_float(ed.y);
            float4 gv = h4_to_f4(*reinterpret_cast<const uint2*>(&g[(size_t)ed.x * DIM + c]));
            acc.x += v0 * gv.x; acc.y += v0 * gv.y;
            acc.z += v0 * gv.z; acc.w += v0 * gv.w;
        }
        acc.x += b4.x; acc.y += b4.y; acc.z += b4.z; acc.w += b4.w;
        __half2 o0 = __floats2half2_rn(acc.x, acc.y);
        __half2 o1 = __floats2half2_rn(acc.z, acc.w);
        uint2 ov;
        ov.x = *reinterpret_cast<uint32_t*>(&o0);
        ov.y = *reinterpret_cast<uint32_t*>(&o1);
        *reinterpret_cast<uint2*>(&h[(size_t)row * DIM + c]) = ov;
        ssum.x += acc.x; ssum.y += acc.y; ssum.z += acc.z; ssum.w += acc.w;
        ssq.x += acc.x * acc.x; ssq.y += acc.y * acc.y;
        ssq.z += acc.z * acc.z; ssq.w += acc.w * acc.w;
    }
    atomicAdd(&red[c], ssum.x);     atomicAdd(&red[c + 1], ssum.y);
    atomicAdd(&red[c + 2], ssum.z); atomicAdd(&red[c + 3], ssum.w);
    atomicAdd(&red[128 + c], ssq.x);     atomicAdd(&red[128 + c + 1], ssq.y);
    atomicAdd(&red[128 + c + 2], ssq.z); atomicAdd(&red[128 + c + 3], ssq.w);
    __syncthreads();
    if (tid < 128) atomicAdd(&g_cs[slot][tid], red[tid]);
    else atomicAdd(&g_cq[slot][tid - 128], red[tid]);
}

// ======================= output GEMM + fused final PairNorm =================
__global__ __launch_bounds__(256) void gemm_out_k(
    const __half* __restrict__ H, const float* __restrict__ Xold,
    const float* __restrict__ W, const float* __restrict__ b,
    float* __restrict__ out, int n, int pn_slot, float n_inv) {
    __shared__ float sx[32 * DIM];
    __shared__ float sw[DIM * CDIM];
    __shared__ float smu[DIM];
    __shared__ float red[DIM];
    int tid = threadIdx.x;
    int row0 = blockIdx.x * 32;
    for (int i = tid; i < DIM * CDIM; i += 256) sw[i] = W[i];
    if (tid < DIM) {
        float mu = g_cs[pn_slot][tid] * n_inv;
        smu[tid] = mu;
        red[tid] = g_cq[pn_slot][tid] * n_inv - mu * mu;
    }
    __syncthreads();
    for (int off = 64; off > 0; off >>= 1) {
        if (tid < off) red[tid] += red[tid + off];
        __syncthreads();
    }
    if (tid == 0) red[0] = rsqrtf(1e-6f + red[0]);
    __syncthreads();
    float s = red[0];
#pragma unroll
    for (int q = 0; q < 4; q++) {
        int flat = (q * 256 + tid) * 4;
        int r = flat >> 7, c = flat & 127;
        int row = row0 + r;
        float4 v = make_float4(0.f, 0.f, 0.f, 0.f);
        if (row < n) {
            float4 hv = h4_to_f4(*reinterpret_cast<const uint2*>(&H[(size_t)row * DIM + c]));
            float4 m = *reinterpret_cast<const float4*>(&smu[c]);
            float4 xo = *reinterpret_cast<const float4*>(&Xold[(size_t)row * DIM + c]);
            v.x = fmaxf((hv.x - m.x) * s, 0.f) + xo.x;
            v.y = fmaxf((hv.y - m.y) * s, 0.f) + xo.y;
            v.z = fmaxf((hv.z - m.z) * s, 0.f) + xo.z;
            v.w = fmaxf((hv.w - m.w) * s, 0.f) + xo.w;
        }
        *reinterpret_cast<float4*>(&sx[flat]) = v;
    }
    __syncthreads();
    int r = tid >> 3;
    int c0 = (tid & 7) * 5;
    float acc[5];
#pragma unroll
    for (int j = 0; j < 5; j++) acc[j] = b[c0 + j];
#pragma unroll 4
    for (int k = 0; k < DIM; k++) {
        float xv = sx[r * DIM + k];
#pragma unroll
        for (int j = 0; j < 5; j++) acc[j] += xv * sw[k * CDIM + c0 + j];
    }
    if (row0 + r < n) {
#pragma unroll
        for (int j = 0; j < 5; j++) out[(size_t)(row0 + r) * CDIM + c0 + j] = acc[j];
    }
}

// ======================= launch =============================================
extern "C" void kernel_launch(void* const* d_in, const int* in_sizes, int n_in,
                              void* d_out, int out_size) {
    const float* x      = (const float*)d_in[0];
    const int*   er     = (const int*)d_in[1];
    const int*   ec     = (const int*)d_in[2];
    const float* ev     = (const float*)d_in[3];
    const float* gamma  = (const float*)d_in[4];
    const float* beta   = (const float*)d_in[5];
    const float* fin_w  = (const float*)d_in[6];
    const float* fin_b  = (const float*)d_in[7];
    const float* gc_w   = (const float*)d_in[8];
    const float* gc_b   = (const float*)d_in[9];
    const float* fout_w = (const float*)d_in[10];
    const float* fout_b = (const float*)d_in[11];
    float* out = (float*)d_out;

    int n = in_sizes[0] / DIM;
    int e = in_sizes[1];
    float n_inv = 1.0f / (float)n;

    float* xbuf;
    __half *g16, *h16;
    cudaGetSymbolAddress((void**)&xbuf, g_xbuf);
    cudaGetSymbolAddress((void**)&g16, g_g16);
    cudaGetSymbolAddress((void**)&h16, g_h16);

    static cudaStream_t s2 = nullptr;
    static cudaEvent_t evFork = nullptr, evJoin = nullptr;
    if (s2 == nullptr) {
        cudaStreamCreateWithFlags(&s2, cudaStreamNonBlocking);
        cudaEventCreateWithFlags(&evFork, cudaEventDisableTiming);
        cudaEventCreateWithFlags(&evJoin, cudaEventDisableTiming);
        cudaFuncSetAttribute(gemm_mma_k, cudaFuncAttributeMaxDynamicSharedMemorySize, GEMM_SMEM_BYTES);
        cudaFuncSetAttribute(gemm_fused_k, cudaFuncAttributeMaxDynamicSharedMemorySize, FUSED_SMEM_BYTES);
    }

    int sblocks = (n + 31) / 32;     // spmm: 8 warps x 4 rows per block
    int nblk = (n + 255) / 256;
    int eblk = (e + 255) / 256;
    const int WMAT = DIM * DIM;

    // ---- fork: branch B (BN stats -> fused GEMM) concurrent with CSR build
    cudaEventRecord(evFork, 0);
    cudaStreamWaitEvent(s2, evFork, 0);

    // branch B (stream s2)
    col_stats_k<<<256, 256, 0, s2>>>(x, n);
    gemm_fused_k<<<NSM, 512, FUSED_SMEM_BYTES, s2>>>(
        x, fin_w, fin_b, gamma, beta, gc_w, g16, n, n_inv);

    // main stream: CSR build
    hist_k<<<eblk, 256>>>(er, e);
    scan1_k<<<nblk, 256>>>(n);
    scan3_k<<<nblk, 256>>>(n, nblk);
    scatter_k<<<eblk, 256>>>(er, ec, ev, e);

    // ---- join
    cudaEventRecord(evJoin, s2);
    cudaStreamWaitEvent(0, evJoin, 0);

    // ---- layer 0 spmm ----
    spmm_k<<<sblocks, 256>>>(g16, gc_b + 0 * DIM, h16, n, 0);

    // ---- layers 1..3: persistent GEMM with fused PairNorm-apply on A ----
    for (int i = 1; i < NLAYER; i++) {
        gemm_mma_k<<<NSM, 512, GEMM_SMEM_BYTES>>>(
            h16, xbuf, xbuf, gc_w + i * WMAT,
            g16, n, (i - 1) & 1, i & 1, (i >= 2) ? 1 : 0, n_inv);
        spmm_k<<<sblocks, 256>>>(g16, gc_b + i * DIM, h16, n, i & 1);
    }

    // ---- output projection with fused final PairNorm (slot 1, addold) ----
    gemm_out_k<<<sblocks, 256>>>(h16, xbuf, fout_w, fout_b, out, n, (NLAYER - 1) & 1, n_inv);
}

// round 16
// speedup vs baseline: 1.6172x; 1.2262x over previous
#include <cuda_runtime.h>
#include <cuda_bf16.h>
#include <cuda_fp16.h>
#include <cstdint>

#define DIM 128
#define CDIM 40
#define NLAYER 4
#define NMAX 50000
#define EMAX 800000
#define NSM 148

// ---------------- device scratch (static: no allocations allowed) ----------
__device__ float  g_xbuf[NMAX * DIM];     // fp32 residual
__device__ __half g_g16[NMAX * DIM];      // fp16 gather buffer (GEMM -> spmm)
__device__ __half g_h16[NMAX * DIM];      // fp16 spmm output (spmm -> GEMM)
__device__ float g_cs[2][DIM];            // PairNorm column sums (parity slots)
__device__ float g_cq[2][DIM];            // PairNorm column sumsq
__device__ float g_bn_ps[256][DIM];       // BN stats partials (no zero needed)
__device__ float g_bn_pq[256][DIM];
__device__ int   g_rowptr[NMAX + 1];
__device__ int   g_cnt[NMAX];             // invariant: zero between replays
__device__ int   g_wcur[NMAX];
__device__ int   g_bsum[256];
__device__ int2  g_edge[EMAX];            // (colidx, val-bits) packed

// ======================= helpers ===========================================
__device__ __forceinline__ uint32_t smem_u32(const void* p) {
    uint32_t a;
    asm("{ .reg .u64 t; cvta.to.shared.u64 t, %1; cvt.u32.u64 %0, t; }" : "=r"(a) : "l"(p));
    return a;
}
__device__ __forceinline__ void ldm_x4(uint32_t* r, uint32_t addr) {
    asm volatile("ldmatrix.sync.aligned.m8n8.x4.shared.b16 {%0,%1,%2,%3}, [%4];"
                 : "=r"(r[0]), "=r"(r[1]), "=r"(r[2]), "=r"(r[3]) : "r"(addr));
}
__device__ __forceinline__ void ldm_x4_t(uint32_t* r, uint32_t addr) {
    asm volatile("ldmatrix.sync.aligned.m8n8.x4.trans.shared.b16 {%0,%1,%2,%3}, [%4];"
                 : "=r"(r[0]), "=r"(r[1]), "=r"(r[2]), "=r"(r[3]) : "r"(addr));
}
// f16 x f16 -> f32 mma (same fragment layout as the bf16 variant)
__device__ __forceinline__ void mma_f16(float* c, const uint32_t* a, const uint32_t* b) {
    asm volatile(
        "mma.sync.aligned.m16n8k16.row.col.f32.f16.f16.f32 "
        "{%0,%1,%2,%3}, {%4,%5,%6,%7}, {%8,%9}, {%0,%1,%2,%3};"
        : "+f"(c[0]), "+f"(c[1]), "+f"(c[2]), "+f"(c[3])
        : "r"(a[0]), "r"(a[1]), "r"(a[2]), "r"(a[3]), "r"(b[0]), "r"(b[1]));
}
// fp16 hi/lo split of an fp32 pair (11+11 mantissa bits; error ~2^-22)
__device__ __forceinline__ uint32_t pack_hi16(float x, float y, uint32_t& lo) {
    __half hx = __float2half(x);
    __half hy = __float2half(y);
    __half lx = __float2half(x - __half2float(hx));
    __half ly = __float2half(y - __half2float(hy));
    lo = (uint32_t)__half_as_ushort(lx) | ((uint32_t)__half_as_ushort(ly) << 16);
    return (uint32_t)__half_as_ushort(hx) | ((uint32_t)__half_as_ushort(hy) << 16);
}
__device__ __forceinline__ float4 h4_to_f4(uint2 hv) {
    float2 lo = __half22float2(*reinterpret_cast<__half2*>(&hv.x));
    float2 hi = __half22float2(*reinterpret_cast<__half2*>(&hv.y));
    return make_float4(lo.x, lo.y, hi.x, hi.y);
}

// ======================= GEMM common pieces =================================
#define PADK 136
#define TILE_B (128 * PADK * 2)
// main gemm: A (1 tile, fp16 exact) + Bh + Bl
#define OFF_A   0
#define OFF_BH  TILE_B
#define OFF_BL  (2 * TILE_B)
#define GEMM_SMEM_BYTES  (3 * TILE_B + 2048)
// fused gemm: Ah + Al (fp32 x split) + B1h + B1l + B2h + B2l
#define F_AH  0
#define F_AL  TILE_B
#define F_B1H (2 * TILE_B)
#define F_B1L (3 * TILE_B)
#define F_B2H (4 * TILE_B)
#define F_B2L (5 * TILE_B)
#define FUSED_SMEM_BYTES (6 * TILE_B + 2048)

// 2-term mainloop: acc += A*(Bh + Bl); A exact fp16.
__device__ __forceinline__ void mma_loop2(uint32_t sb, int aOff, int bOffH, int bOffL,
                                          int wm, int wn, int lane,
                                          float acc[2][4][4]) {
    int lrow = lane & 15;
    int lcol8 = (lane >> 4) << 3;
#pragma unroll
    for (int k0 = 0; k0 < 128; k0 += 16) {
        uint32_t a[2][4];
#pragma unroll
        for (int mg = 0; mg < 2; mg++)
            ldm_x4(a[mg], sb + aOff + (uint32_t)((wm + mg * 16 + lrow) * PADK + k0 + lcol8) * 2u);
        uint32_t bh[2][4], bl[2][4];
#pragma unroll
        for (int nc = 0; nc < 2; nc++) {
            uint32_t boff = (uint32_t)((k0 + lrow) * PADK + wn + nc * 16 + lcol8) * 2u;
            ldm_x4_t(bh[nc], sb + bOffH + boff);
            ldm_x4_t(bl[nc], sb + bOffL + boff);
        }
#pragma unroll
        for (int mg = 0; mg < 2; mg++)
#pragma unroll
            for (int ng = 0; ng < 4; ng++) {
                mma_f16(acc[mg][ng], a[mg], &bh[ng >> 1][(ng & 1) * 2]);
                mma_f16(acc[mg][ng], a[mg], &bl[ng >> 1][(ng & 1) * 2]);
            }
    }
}

// 3-term mainloop (A split): acc += Ah*Bh + Ah*Bl + Al*Bh.
__device__ __forceinline__ void mma_loop3(uint32_t sb, int ahOff, int alOff,
                                          int bOffH, int bOffL,
                                          int wm, int wn, int lane,
                                          float acc[2][4][4]) {
    int lrow = lane & 15;
    int lcol8 = (lane >> 4) << 3;
#pragma unroll
    for (int t = 0; t < 3; t++) {
        int aOff = (t == 2) ? alOff : ahOff;
        int bOff = (t == 1) ? bOffL : bOffH;
#pragma unroll
        for (int k0 = 0; k0 < 128; k0 += 16) {
            uint32_t a[2][4];
#pragma unroll
            for (int mg = 0; mg < 2; mg++)
                ldm_x4(a[mg], sb + aOff + (uint32_t)((wm + mg * 16 + lrow) * PADK + k0 + lcol8) * 2u);
            uint32_t b[2][4];
#pragma unroll
            for (int nc = 0; nc < 2; nc++)
                ldm_x4_t(b[nc], sb + bOff + (uint32_t)((k0 + lrow) * PADK + wn + nc * 16 + lcol8) * 2u);
#pragma unroll
            for (int mg = 0; mg < 2; mg++)
#pragma unroll
                for (int ng = 0; ng < 4; ng++)
                    mma_f16(acc[mg][ng], a[mg], &b[ng >> 1][(ng & 1) * 2]);
        }
    }
}

// stage a weight matrix from fp32 gmem, splitting to fp16 hi/lo in smem.
__device__ __forceinline__ void stage_B16(char* sm, int offH, int offL,
                                          const float* __restrict__ W,
                                          const float* rscale, int tid) {
    for (int g = tid; g < 4096; g += 512) {
        int r = g >> 5, c = (g & 31) * 4;
        float4 w = *reinterpret_cast<const float4*>(&W[r * DIM + c]);
        if (rscale) {
            float s = rscale[r];
            w.x *= s; w.y *= s; w.z *= s; w.w *= s;
        }
        uint32_t eoff = (uint32_t)(r * PADK + c) * 2u;
        uint32_t l0, l1;
        uint32_t h0 = pack_hi16(w.x, w.y, l0);
        uint32_t h1 = pack_hi16(w.z, w.w, l1);
        *reinterpret_cast<uint2*>(sm + offH + eoff) = make_uint2(h0, h1);
        *reinterpret_cast<uint2*>(sm + offL + eoff) = make_uint2(l0, l1);
    }
}

// ======================= main GEMM (persistent, fused PairNorm on A) ========
// A fp16 (exact, no split); weights split fp16 hi/lo; C fp16.
__global__ __launch_bounds__(512) void gemm_mma_k(
    const __half* __restrict__ A, const float* __restrict__ Xold,
    float* __restrict__ Xwrite, const float* __restrict__ Wf32,
    __half* __restrict__ C, int n,
    int pn_slot, int zero_slot, int addold, float n_inv) {
    extern __shared__ char sm[];
    float* smu = reinterpret_cast<float*>(sm + 3 * TILE_B);
    float* red = smu + DIM;
    uint32_t sb = smem_u32(sm);
    int tid = threadIdx.x, wid = tid >> 5, lane = tid & 31;

    if (zero_slot >= 0 && blockIdx.x == 0 && tid < DIM) {
        g_cs[zero_slot][tid] = 0.f;
        g_cq[zero_slot][tid] = 0.f;
    }

    if (tid < DIM) {
        float mu = g_cs[pn_slot][tid] * n_inv;
        smu[tid] = mu;
        red[tid] = g_cq[pn_slot][tid] * n_inv - mu * mu;
    }
    __syncthreads();
    for (int off = 64; off > 0; off >>= 1) {
        if (tid < off) red[tid] += red[tid + off];
        __syncthreads();
    }
    if (tid == 0) red[0] = rsqrtf(1e-6f + red[0]);
    __syncthreads();
    float pscale = red[0];

    int T = (n + 127) >> 7;
    int t = blockIdx.x;
    if (t >= T) return;

    stage_B16(sm, OFF_BH, OFF_BL, Wf32, nullptr, tid);

    // stage first tile A: PN + residual (fp32), write Xwrite, store fp16
    {
        int row0 = t * 128;
        for (int g = tid; g < 4096; g += 512) {
            int r = g >> 5, c = (g & 31) * 4;
            int row = row0 + r;
            float4 av = make_float4(0.f, 0.f, 0.f, 0.f);
            if (row < n) {
                av = h4_to_f4(*reinterpret_cast<const uint2*>(&A[(size_t)row * DIM + c]));
                float4 m = *reinterpret_cast<const float4*>(&smu[c]);
                av.x = fmaxf((av.x - m.x) * pscale, 0.f);
                av.y = fmaxf((av.y - m.y) * pscale, 0.f);
                av.z = fmaxf((av.z - m.z) * pscale, 0.f);
                av.w = fmaxf((av.w - m.w) * pscale, 0.f);
                if (addold) {
                    float4 xo = *reinterpret_cast<const float4*>(&Xold[(size_t)row * DIM + c]);
                    av.x += xo.x; av.y += xo.y; av.z += xo.z; av.w += xo.w;
                }
                *reinterpret_cast<float4*>(&Xwrite[(size_t)row * DIM + c]) = av;
            }
            __half2 p0 = __floats2half2_rn(av.x, av.y);
            __half2 p1 = __floats2half2_rn(av.z, av.w);
            uint32_t eoff = (uint32_t)(r * PADK + c) * 2u;
            *reinterpret_cast<uint2*>(sm + OFF_A + eoff) =
                make_uint2(*reinterpret_cast<uint32_t*>(&p0), *reinterpret_cast<uint32_t*>(&p1));
        }
    }
    __syncthreads();

    int wm = (wid & 3) * 32;
    int wn = (wid >> 2) * 32;

    while (true) {
        int tn = t + gridDim.x;
        bool hn = tn < T;
        uint2 raw[8];
        if (hn) {
            int row0n = tn * 128;
#pragma unroll
            for (int q = 0; q < 8; q++) {
                int g = q * 512 + tid;
                int r = g >> 5, c = (g & 31) * 4;
                int row = row0n + r;
                raw[q] = (row < n)
                    ? *reinterpret_cast<const uint2*>(&A[(size_t)row * DIM + c])
                    : make_uint2(0u, 0u);
            }
        }

        float acc[2][4][4];
#pragma unroll
        for (int mg = 0; mg < 2; mg++)
#pragma unroll
            for (int ng = 0; ng < 4; ng++)
#pragma unroll
                for (int q = 0; q < 4; q++) acc[mg][ng][q] = 0.f;

        mma_loop2(sb, OFF_A, OFF_BH, OFF_BL, wm, wn, lane, acc);

        int row0 = t * 128;
        int rbase = row0 + wm + (lane >> 2);
        int cbase = wn + (lane & 3) * 2;
#pragma unroll
        for (int mg = 0; mg < 2; mg++)
#pragma unroll
            for (int half = 0; half < 2; half++) {
                int row = rbase + mg * 16 + half * 8;
                if (row < n) {
#pragma unroll
                    for (int ng = 0; ng < 4; ng++) {
                        int col = cbase + ng * 8;
                        __half2 o = __floats2half2_rn(acc[mg][ng][half * 2],
                                                      acc[mg][ng][half * 2 + 1]);
                        *reinterpret_cast<__half2*>(&C[(size_t)row * DIM + col]) = o;
                    }
                }
            }

        if (!hn) break;
        __syncthreads();
        {
            int row0n = tn * 128;
#pragma unroll
            for (int q = 0; q < 8; q++) {
                int g = q * 512 + tid;
                int r = g >> 5, c = (g & 31) * 4;
                int row = row0n + r;
                float4 av = make_float4(0.f, 0.f, 0.f, 0.f);
                if (row < n) {
                    av = h4_to_f4(raw[q]);
                    float4 m = *reinterpret_cast<const float4*>(&smu[c]);
                    av.x = fmaxf((av.x - m.x) * pscale, 0.f);
                    av.y = fmaxf((av.y - m.y) * pscale, 0.f);
                    av.z = fmaxf((av.z - m.z) * pscale, 0.f);
                    av.w = fmaxf((av.w - m.w) * pscale, 0.f);
                    if (addold) {
                        float4 xo = *reinterpret_cast<const float4*>(&Xold[(size_t)row * DIM + c]);
                        av.x += xo.x; av.y += xo.y; av.z += xo.z; av.w += xo.w;
                    }
                    *reinterpret_cast<float4*>(&Xwrite[(size_t)row * DIM + c]) = av;
                }
                __half2 p0 = __floats2half2_rn(av.x, av.y);
                __half2 p1 = __floats2half2_rn(av.z, av.w);
                uint32_t eoff = (uint32_t)(r * PADK + c) * 2u;
                *reinterpret_cast<uint2*>(sm + OFF_A + eoff) =
                    make_uint2(*reinterpret_cast<uint32_t*>(&p0), *reinterpret_cast<uint32_t*>(&p1));
            }
        }
        __syncthreads();
        t = tn;
    }
}

// ======================= fused fc_in + layer-0 GEMM (persistent) ============
// First GEMM: A = x (fp32) split fp16 hi/lo, 3 terms. Second: A fp16, 2 terms.
__global__ __launch_bounds__(512) void gemm_fused_k(
    const float* __restrict__ X,
    const float* __restrict__ fin_w, const float* __restrict__ fin_b,
    const float* __restrict__ gamma, const float* __restrict__ beta,
    const float* __restrict__ W2,
    __half* __restrict__ C, int n, float n_inv) {
    extern __shared__ char sm[];
    float* ssc = reinterpret_cast<float*>(sm + 6 * TILE_B);
    float* ssh = ssc + DIM;
    float* sbias = ssh + DIM;
    uint32_t sb = smem_u32(sm);
    int tid = threadIdx.x, wid = tid >> 5, lane = tid & 31;

    if (blockIdx.x == 0 && tid < DIM) {
        g_cs[0][tid] = 0.f;
        g_cq[0][tid] = 0.f;
    }
    if (tid < DIM) {
        float s0 = 0.f, s1 = 0.f, s2 = 0.f, s3 = 0.f;
        float q0 = 0.f, q1 = 0.f, q2 = 0.f, q3 = 0.f;
        for (int p = 0; p < 256; p += 4) {
            s0 += g_bn_ps[p][tid];     s1 += g_bn_ps[p + 1][tid];
            s2 += g_bn_ps[p + 2][tid]; s3 += g_bn_ps[p + 3][tid];
            q0 += g_bn_pq[p][tid];     q1 += g_bn_pq[p + 1][tid];
            q2 += g_bn_pq[p + 2][tid]; q3 += g_bn_pq[p + 3][tid];
        }
        float mu = ((s0 + s1) + (s2 + s3)) * n_inv;
        float var = ((q0 + q1) + (q2 + q3)) * n_inv - mu * mu;
        float s = gamma[tid] * rsqrtf(var + 1e-5f);
        ssc[tid] = s;
        ssh[tid] = beta[tid] - mu * s;
    }
    __syncthreads();

    int T = (n + 127) >> 7;
    int t = blockIdx.x;
    if (t >= T) return;

    stage_B16(sm, F_B1H, F_B1L, fin_w, ssc, tid);
    stage_B16(sm, F_B2H, F_B2L, W2, nullptr, tid);
    if (tid < DIM) {
        float acc = fin_b[tid];
        for (int d = 0; d < DIM; d++) acc += ssh[d] * fin_w[d * DIM + tid];
        sbias[tid] = acc;
    }

    // stage first tile (fp32 x -> fp16 hi/lo split)
    {
        int row0 = t * 128;
        for (int g = tid; g < 4096; g += 512) {
            int r = g >> 5, c = (g & 31) * 4;
            int row = row0 + r;
            float4 av = make_float4(0.f, 0.f, 0.f, 0.f);
            if (row < n) av = *reinterpret_cast<const float4*>(&X[(size_t)row * DIM + c]);
            uint32_t eoff = (uint32_t)(r * PADK + c) * 2u;
            uint32_t al0, al1;
            uint32_t ah0 = pack_hi16(av.x, av.y, al0);
            uint32_t ah1 = pack_hi16(av.z, av.w, al1);
            *reinterpret_cast<uint2*>(sm + F_AH + eoff) = make_uint2(ah0, ah1);
            *reinterpret_cast<uint2*>(sm + F_AL + eoff) = make_uint2(al0, al1);
        }
    }
    __syncthreads();

    int wm = (wid & 3) * 32;
    int wn = (wid >> 2) * 32;

    while (true) {
        int tn = t + gridDim.x;
        bool hn = tn < T;
        float4 raw[8];
        if (hn) {
            int row0n = tn * 128;
#pragma unroll
            for (int q = 0; q < 8; q++) {
                int g = q * 512 + tid;
                int r = g >> 5, c = (g & 31) * 4;
                int row = row0n + r;
                raw[q] = (row < n)
                    ? *reinterpret_cast<const float4*>(&X[(size_t)row * DIM + c])
                    : make_float4(0.f, 0.f, 0.f, 0.f);
            }
        }

        float acc[2][4][4];
#pragma unroll
        for (int mg = 0; mg < 2; mg++)
#pragma unroll
            for (int ng = 0; ng < 4; ng++)
#pragma unroll
                for (int q = 0; q < 4; q++) acc[mg][ng][q] = 0.f;

        mma_loop3(sb, F_AH, F_AL, F_B1H, F_B1L, wm, wn, lane, acc);
        __syncthreads();   // all warps done reading A tiles

        // write intermediate (acc + bias) into F_AH as plain fp16 (exact input
        // for the 2-term second GEMM)
        {
            int rl = wm + (lane >> 2);
            int cb = wn + (lane & 3) * 2;
#pragma unroll
            for (int mg = 0; mg < 2; mg++)
#pragma unroll
                for (int half = 0; half < 2; half++) {
                    int r = rl + mg * 16 + half * 8;
#pragma unroll
                    for (int ng = 0; ng < 4; ng++) {
                        int col = cb + ng * 8;
                        float v0 = acc[mg][ng][half * 2] + sbias[col];
                        float v1 = acc[mg][ng][half * 2 + 1] + sbias[col + 1];
                        __half2 p = __floats2half2_rn(v0, v1);
                        uint32_t eoff = (uint32_t)(r * PADK + col) * 2u;
                        *reinterpret_cast<uint32_t*>(sm + F_AH + eoff) =
                            *reinterpret_cast<uint32_t*>(&p);
                    }
                }
        }
        __syncthreads();

#pragma unroll
        for (int mg = 0; mg < 2; mg++)
#pragma unroll
            for (int ng = 0; ng < 4; ng++)
#pragma unroll
                for (int q = 0; q < 4; q++) acc[mg][ng][q] = 0.f;

        mma_loop2(sb, F_AH, F_B2H, F_B2L, wm, wn, lane, acc);

        int row0 = t * 128;
        int rbase = row0 + wm + (lane >> 2);
        int cbase = wn + (lane & 3) * 2;
#pragma unroll
        for (int mg = 0; mg < 2; mg++)
#pragma unroll
            for (int half = 0; half < 2; half++) {
                int row = rbase + mg * 16 + half * 8;
                if (row < n) {
#pragma unroll
                    for (int ng = 0; ng < 4; ng++) {
                        int col = cbase + ng * 8;
                        __half2 o = __floats2half2_rn(acc[mg][ng][half * 2],
                                                      acc[mg][ng][half * 2 + 1]);
                        *reinterpret_cast<__half2*>(&C[(size_t)row * DIM + col]) = o;
                    }
                }
            }

        if (!hn) break;
        __syncthreads();
        {
#pragma unroll
            for (int q = 0; q < 8; q++) {
                int g = q * 512 + tid;
                int r = g >> 5, c = (g & 31) * 4;
                float4 av = raw[q];
                uint32_t eoff = (uint32_t)(r * PADK + c) * 2u;
                uint32_t al0, al1;
                uint32_t ah0 = pack_hi16(av.x, av.y, al0);
                uint32_t ah1 = pack_hi16(av.z, av.w, al1);
                *reinterpret_cast<uint2*>(sm + F_AH + eoff) = make_uint2(ah0, ah1);
                *reinterpret_cast<uint2*>(sm + F_AL + eoff) = make_uint2(al0, al1);
            }
        }
        __syncthreads();
        t = tn;
    }
}

// ======================= input BN stats -> per-block partials ===============
__global__ __launch_bounds__(256) void col_stats_k(const float* __restrict__ x, int n) {
    __shared__ float red[256];
    __shared__ float redq[128];
    int tid = threadIdx.x;
    red[tid] = 0.f;
    if (tid < 128) redq[tid] = 0.f;
    int w = tid >> 5, lane = tid & 31, c = lane * 4;
    int gw = blockIdx.x * 8 + w;
    const int STR = 256 * 8;
    float4 s = make_float4(0.f, 0.f, 0.f, 0.f);
    float4 q = make_float4(0.f, 0.f, 0.f, 0.f);
    __syncthreads();
    for (int r0 = gw; r0 < n; r0 += STR * 4) {
#pragma unroll
        for (int u = 0; u < 4; u++) {
            int row = r0 + u * STR;
            if (row < n) {
                float4 v = *reinterpret_cast<const float4*>(&x[(size_t)row * DIM + c]);
                s.x += v.x; s.y += v.y; s.z += v.z; s.w += v.w;
                q.x += v.x * v.x; q.y += v.y * v.y; q.z += v.z * v.z; q.w += v.w * v.w;
            }
        }
    }
    atomicAdd(&red[c], s.x);     atomicAdd(&red[c + 1], s.y);
    atomicAdd(&red[c + 2], s.z); atomicAdd(&red[c + 3], s.w);
    atomicAdd(&redq[c], q.x);     atomicAdd(&redq[c + 1], q.y);
    atomicAdd(&redq[c + 2], q.z); atomicAdd(&redq[c + 3], q.w);
    __syncthreads();
    if (tid < 128) {
        g_bn_ps[blockIdx.x][tid] = red[tid];
        g_bn_pq[blockIdx.x][tid] = redq[tid];
    }
}

// ======================= CSR build ==========================================
__global__ void hist_k(const int* __restrict__ er, int e) {
    int i = blockIdx.x * blockDim.x + threadIdx.x;
    if (i < e) atomicAdd(&g_cnt[er[i]], 1);
}

__global__ __launch_bounds__(256) void scan1_k(int n) {
    __shared__ int red[256];
    int tid = threadIdx.x;
    int i = blockIdx.x * 256 + tid;
    red[tid] = (i < n) ? g_cnt[i] : 0;
    __syncthreads();
    for (int off = 128; off > 0; off >>= 1) {
        if (tid < off) red[tid] += red[tid + off];
        __syncthreads();
    }
    if (tid == 0) g_bsum[blockIdx.x] = red[0];
}

__global__ __launch_bounds__(256) void scan3_k(int n, int nblk) {
    __shared__ int bs[256];
    __shared__ int s[256];
    int tid = threadIdx.x;
    bs[tid] = (tid < nblk) ? g_bsum[tid] : 0;
    __syncthreads();
    for (int off = 1; off < 256; off <<= 1) {
        int t = (tid >= off) ? bs[tid - off] : 0;
        __syncthreads();
        bs[tid] += t;
        __syncthreads();
    }
    int bpref = (blockIdx.x == 0) ? 0 : bs[blockIdx.x - 1];
    if (blockIdx.x == 0 && tid == 0) g_rowptr[n] = bs[255];
    int i = blockIdx.x * 256 + tid;
    int v = (i < n) ? g_cnt[i] : 0;
    s[tid] = v;
    __syncthreads();
    for (int off = 1; off < 256; off <<= 1) {
        int t = (tid >= off) ? s[tid - off] : 0;
        __syncthreads();
        s[tid] += t;
        __syncthreads();
    }
    if (i < n) {
        int excl = s[tid] - v + bpref;
        g_rowptr[i] = excl;
        g_wcur[i] = excl;
        g_cnt[i] = 0;
    }
}

__global__ void scatter_k(const int* __restrict__ er, const int* __restrict__ ec,
                          const float* __restrict__ ev, int e) {
    int i = blockIdx.x * blockDim.x + threadIdx.x;
    if (i < e) {
        int r = er[i];
        int pos = atomicAdd(&g_wcur[r], 1);
        g_edge[pos] = make_int2(ec[i], __float_as_int(ev[i]));
    }
}

// ======================= SPMM (fp16 in/out) + fused PairNorm stats ==========
__global__ __launch_bounds__(256) void spmm_k(
    const __half* __restrict__ g, const float* __restrict__ bias,
    __half* __restrict__ h, int n, int slot) {
    __shared__ float red[256];
    int tid = threadIdx.x;
    red[tid] = 0.f;
    int w = tid >> 5, lane = tid & 31;
    int gw = blockIdx.x * 8 + w;
    int c = lane * 4;
    float4 b4 = *reinterpret_cast<const float4*>(&bias[c]);
    float4 ssum = make_float4(0.f, 0.f, 0.f, 0.f);
    float4 ssq = make_float4(0.f, 0.f, 0.f, 0.f);
    __syncthreads();
#pragma unroll
    for (int rr = 0; rr < 4; rr++) {
        int row = gw * 4 + rr;
        if (row >= n) break;
        int s = g_rowptr[row];
        int e = g_rowptr[row + 1];
        float4 acc = make_float4(0.f, 0.f, 0.f, 0.f);
        int i = s;
        for (; i + 7 < e; i += 8) {
            uint2 p[8];
            float vv[8];
#pragma unroll
            for (int u = 0; u < 8; u++) {
                int2 ed = g_edge[i + u];
                vv[u] = __int_as_float(ed.y);
                p[u] = *reinterpret_cast<const uint2*>(&g[(size_t)ed.x * DIM + c]);
            }
#pragma unroll
            for (int u = 0; u < 8; u++) {
                float4 gv = h4_to_f4(p[u]);
                acc.x += vv[u] * gv.x;
                acc.y += vv[u] * gv.y;
                acc.z += vv[u] * gv.z;
                acc.w += vv[u] * gv.w;
            }
        }
        if (i + 3 < e) {
            uint2 p[4];
            float vv[4];
#pragma unroll
            for (int u = 0; u < 4; u++) {
                int2 ed = g_edge[i + u];
                vv[u] = __int_as_float(ed.y);
                p[u] = *reinterpret_cast<const uint2*>(&g[(size_t)ed.x * DIM + c]);
            }
#pragma unroll
            for (int u = 0; u < 4; u++) {
                float4 gv = h4_to_f4(p[u]);
                acc.x += vv[u] * gv.x;
                acc.y += vv[u] * gv.y;
                acc.z += vv[u] * gv.z;
                acc.w += vv[u] * gv.w;
            }
            i += 4;
        }
        for (; i < e; i++) {
            int2 ed = g_edge[i];
            float v0 = __int_as_float(ed.y);
            float4 gv = h4_to_f4(*reinterpret_cast<const uint2*>(&g[(size_t)ed.x * DIM + c]));
            acc.x += v0 * gv.x; acc.y += v0 * gv.y;
            acc.z += v0 * gv.z; acc.w += v0 * gv.w;
        }
        acc.x += b4.x; acc.y += b4.y; acc.z += b4.z; acc.w += b4.w;
        __half2 o0 = __floats2half2_rn(acc.x, acc.y);
        __half2 o1 = __floats2half2_rn(acc.z, acc.w);
        uint2 ov;
        ov.x = *reinterpret_cast<uint32_t*>(&o0);
        ov.y = *reinterpret_cast<uint32_t*>(&o1);
        *reinterpret_cast<uint2*>(&h[(size_t)row * DIM + c]) = ov;
        ssum.x += acc.x; ssum.y += acc.y; ssum.z += acc.z; ssum.w += acc.w;
        ssq.x += acc.x * acc.x; ssq.y += acc.y * acc.y;
        ssq.z += acc.z * acc.z; ssq.w += acc.w * acc.w;
    }
    atomicAdd(&red[c], ssum.x);     atomicAdd(&red[c + 1], ssum.y);
    atomicAdd(&red[c + 2], ssum.z); atomicAdd(&red[c + 3], ssum.w);
    atomicAdd(&red[128 + c], ssq.x);     atomicAdd(&red[128 + c + 1], ssq.y);
    atomicAdd(&red[128 + c + 2], ssq.z); atomicAdd(&red[128 + c + 3], ssq.w);
    __syncthreads();
    if (tid < 128) atomicAdd(&g_cs[slot][tid], red[tid]);
    else atomicAdd(&g_cq[slot][tid - 128], red[tid]);
}

// ======================= output GEMM + fused final PairNorm =================
__global__ __launch_bounds__(256) void gemm_out_k(
    const __half* __restrict__ H, const float* __restrict__ Xold,
    const float* __restrict__ W, const float* __restrict__ b,
    float* __restrict__ out, int n, int pn_slot, float n_inv) {
    __shared__ float sx[32 * DIM];
    __shared__ float sw[DIM * CDIM];
    __shared__ float smu[DIM];
    __shared__ float red[DIM];
    int tid = threadIdx.x;
    int row0 = blockIdx.x * 32;
    for (int i = tid; i < DIM * CDIM; i += 256) sw[i] = W[i];
    if (tid < DIM) {
        float mu = g_cs[pn_slot][tid] * n_inv;
        smu[tid] = mu;
        red[tid] = g_cq[pn_slot][tid] * n_inv - mu * mu;
    }
    __syncthreads();
    for (int off = 64; off > 0; off >>= 1) {
        if (tid < off) red[tid] += red[tid + off];
        __syncthreads();
    }
    if (tid == 0) red[0] = rsqrtf(1e-6f + red[0]);
    __syncthreads();
    float s = red[0];
#pragma unroll
    for (int q = 0; q < 4; q++) {
        int flat = (q * 256 + tid) * 4;
        int r = flat >> 7, c = flat & 127;
        int row = row0 + r;
        float4 v = make_float4(0.f, 0.f, 0.f, 0.f);
        if (row < n) {
            float4 hv = h4_to_f4(*reinterpret_cast<const uint2*>(&H[(size_t)row * DIM + c]));
            float4 m = *reinterpret_cast<const float4*>(&smu[c]);
            float4 xo = *reinterpret_cast<const float4*>(&Xold[(size_t)row * DIM + c]);
            v.x = fmaxf((hv.x - m.x) * s, 0.f) + xo.x;
            v.y = fmaxf((hv.y - m.y) * s, 0.f) + xo.y;
            v.z = fmaxf((hv.z - m.z) * s, 0.f) + xo.z;
            v.w = fmaxf((hv.w - m.w) * s, 0.f) + xo.w;
        }
        *reinterpret_cast<float4*>(&sx[flat]) = v;
    }
    __syncthreads();
    int r = tid >> 3;
    int c0 = (tid & 7) * 5;
    float acc[5];
#pragma unroll
    for (int j = 0; j < 5; j++) acc[j] = b[c0 + j];
#pragma unroll 4
    for (int k = 0; k < DIM; k++) {
        float xv = sx[r * DIM + k];
#pragma unroll
        for (int j = 0; j < 5; j++) acc[j] += xv * sw[k * CDIM + c0 + j];
    }
    if (row0 + r < n) {
#pragma unroll
        for (int j = 0; j < 5; j++) out[(size_t)(row0 + r) * CDIM + c0 + j] = acc[j];
    }
}

// ======================= launch =============================================
extern "C" void kernel_launch(void* const* d_in, const int* in_sizes, int n_in,
                              void* d_out, int out_size) {
    const float* x      = (const float*)d_in[0];
    const int*   er     = (const int*)d_in[1];
    const int*   ec     = (const int*)d_in[2];
    const float* ev     = (const float*)d_in[3];
    const float* gamma  = (const float*)d_in[4];
    const float* beta   = (const float*)d_in[5];
    const float* fin_w  = (const float*)d_in[6];
    const float* fin_b  = (const float*)d_in[7];
    const float* gc_w   = (const float*)d_in[8];
    const float* gc_b   = (const float*)d_in[9];
    const float* fout_w = (const float*)d_in[10];
    const float* fout_b = (const float*)d_in[11];
    float* out = (float*)d_out;

    int n = in_sizes[0] / DIM;
    int e = in_sizes[1];
    float n_inv = 1.0f / (float)n;

    float* xbuf;
    __half *g16, *h16;
    cudaGetSymbolAddress((void**)&xbuf, g_xbuf);
    cudaGetSymbolAddress((void**)&g16, g_g16);
    cudaGetSymbolAddress((void**)&h16, g_h16);

    static cudaStream_t s2 = nullptr;
    static cudaEvent_t evFork = nullptr, evJoin = nullptr;
    if (s2 == nullptr) {
        cudaStreamCreateWithFlags(&s2, cudaStreamNonBlocking);
        cudaEventCreateWithFlags(&evFork, cudaEventDisableTiming);
        cudaEventCreateWithFlags(&evJoin, cudaEventDisableTiming);
        cudaFuncSetAttribute(gemm_mma_k, cudaFuncAttributeMaxDynamicSharedMemorySize, GEMM_SMEM_BYTES);
        cudaFuncSetAttribute(gemm_fused_k, cudaFuncAttributeMaxDynamicSharedMemorySize, FUSED_SMEM_BYTES);
    }

    int sblocks = (n + 31) / 32;     // spmm: 8 warps x 4 rows per block
    int nblk = (n + 255) / 256;
    int eblk = (e + 255) / 256;
    const int WMAT = DIM * DIM;

    // ---- fork: branch B (BN stats -> fused GEMM) concurrent with CSR build
    cudaEventRecord(evFork, 0);
    cudaStreamWaitEvent(s2, evFork, 0);

    // branch B (stream s2)
    col_stats_k<<<256, 256, 0, s2>>>(x, n);
    gemm_fused_k<<<NSM, 512, FUSED_SMEM_BYTES, s2>>>(
        x, fin_w, fin_b, gamma, beta, gc_w, g16, n, n_inv);

    // main stream: CSR build
    hist_k<<<eblk, 256>>>(er, e);
    scan1_k<<<nblk, 256>>>(n);
    scan3_k<<<nblk, 256>>>(n, nblk);
    scatter_k<<<eblk, 256>>>(er, ec, ev, e);

    // ---- join
    cudaEventRecord(evJoin, s2);
    cudaStreamWaitEvent(0, evJoin, 0);

    // ---- layer 0 spmm ----
    spmm_k<<<sblocks, 256>>>(g16, gc_b + 0 * DIM, h16, n, 0);

    // ---- layers 1..3: persistent GEMM with fused PairNorm-apply on A ----
    for (int i = 1; i < NLAYER; i++) {
        gemm_mma_k<<<NSM, 512, GEMM_SMEM_BYTES>>>(
            h16, xbuf, xbuf, gc_w + i * WMAT,
            g16, n, (i - 1) & 1, i & 1, (i >= 2) ? 1 : 0, n_inv);
        spmm_k<<<sblocks, 256>>>(g16, gc_b + i * DIM, h16, n, i & 1);
    }

    // ---- output projection with fused final PairNorm (slot 1, addold) ----
    gemm_out_k<<<sblocks, 256>>>(h16, xbuf, fout_w, fout_b, out, n, (NLAYER - 1) & 1, n_inv);
}

// round 17
// speedup vs baseline: 1.6224x; 1.0032x over previous
#include <cuda_runtime.h>
#include <cuda_bf16.h>
#include <cuda_fp16.h>
#include <cstdint>

#define DIM 128
#define CDIM 40
#define NLAYER 4
#define NMAX 50000
#define EMAX 800000
#define NSM 148

// ---------------- device scratch (static: no allocations allowed) ----------
__device__ float  g_xbuf[NMAX * DIM];     // fp32 residual
__device__ __half g_g16[NMAX * DIM];      // fp16 gather buffer (GEMM -> spmm)
__device__ __half g_h16[NMAX * DIM];      // fp16 spmm output (spmm -> GEMM)
__device__ float g_cs[2][DIM];            // PairNorm column sums (parity slots)
__device__ float g_cq[2][DIM];            // PairNorm column sumsq
__device__ float g_bn_ps[256][DIM];       // BN stats partials (no zero needed)
__device__ float g_bn_pq[256][DIM];
__device__ int   g_rowptr[NMAX + 1];
__device__ int   g_cnt[NMAX];             // invariant: zero between replays
__device__ int   g_wcur[NMAX];
__device__ int   g_bsum[256];
__device__ int2  g_edge[EMAX];            // (colidx, val-bits) packed

// ======================= helpers ===========================================
__device__ __forceinline__ uint32_t smem_u32(const void* p) {
    uint32_t a;
    asm("{ .reg .u64 t; cvta.to.shared.u64 t, %1; cvt.u32.u64 %0, t; }" : "=r"(a) : "l"(p));
    return a;
}
__device__ __forceinline__ void ldm_x4(uint32_t* r, uint32_t addr) {
    asm volatile("ldmatrix.sync.aligned.m8n8.x4.shared.b16 {%0,%1,%2,%3}, [%4];"
                 : "=r"(r[0]), "=r"(r[1]), "=r"(r[2]), "=r"(r[3]) : "r"(addr));
}
__device__ __forceinline__ void ldm_x4_t(uint32_t* r, uint32_t addr) {
    asm volatile("ldmatrix.sync.aligned.m8n8.x4.trans.shared.b16 {%0,%1,%2,%3}, [%4];"
                 : "=r"(r[0]), "=r"(r[1]), "=r"(r[2]), "=r"(r[3]) : "r"(addr));
}
// f16 x f16 -> f32 mma (same fragment layout as the bf16 variant)
__device__ __forceinline__ void mma_f16(float* c, const uint32_t* a, const uint32_t* b) {
    asm volatile(
        "mma.sync.aligned.m16n8k16.row.col.f32.f16.f16.f32 "
        "{%0,%1,%2,%3}, {%4,%5,%6,%7}, {%8,%9}, {%0,%1,%2,%3};"
        : "+f"(c[0]), "+f"(c[1]), "+f"(c[2]), "+f"(c[3])
        : "r"(a[0]), "r"(a[1]), "r"(a[2]), "r"(a[3]), "r"(b[0]), "r"(b[1]));
}
// fp16 hi/lo split of an fp32 pair (11+11 mantissa bits; error ~2^-22)
__device__ __forceinline__ uint32_t pack_hi16(float x, float y, uint32_t& lo) {
    __half hx = __float2half(x);
    __half hy = __float2half(y);
    __half lx = __float2half(x - __half2float(hx));
    __half ly = __float2half(y - __half2float(hy));
    lo = (uint32_t)__half_as_ushort(lx) | ((uint32_t)__half_as_ushort(ly) << 16);
    return (uint32_t)__half_as_ushort(hx) | ((uint32_t)__half_as_ushort(hy) << 16);
}
__device__ __forceinline__ float4 h4_to_f4(uint2 hv) {
    float2 lo = __half22float2(*reinterpret_cast<__half2*>(&hv.x));
    float2 hi = __half22float2(*reinterpret_cast<__half2*>(&hv.y));
    return make_float4(lo.x, lo.y, hi.x, hi.y);
}

// ======================= GEMM common pieces =================================
#define PADK 136
#define TILE_B (128 * PADK * 2)
// main gemm: A (1 tile, fp16 exact) + Bh + Bl
#define OFF_A   0
#define OFF_BH  TILE_B
#define OFF_BL  (2 * TILE_B)
#define GEMM_SMEM_BYTES  (3 * TILE_B + 2048)
// fused gemm: Ah + Al (fp32 x split) + B1h + B1l + B2h + B2l
#define F_AH  0
#define F_AL  TILE_B
#define F_B1H (2 * TILE_B)
#define F_B1L (3 * TILE_B)
#define F_B2H (4 * TILE_B)
#define F_B2L (5 * TILE_B)
#define FUSED_SMEM_BYTES (6 * TILE_B + 2048)

// 2-term mainloop: acc += A*(Bh + Bl); A exact fp16.
__device__ __forceinline__ void mma_loop2(uint32_t sb, int aOff, int bOffH, int bOffL,
                                          int wm, int wn, int lane,
                                          float acc[2][4][4]) {
    int lrow = lane & 15;
    int lcol8 = (lane >> 4) << 3;
#pragma unroll
    for (int k0 = 0; k0 < 128; k0 += 16) {
        uint32_t a[2][4];
#pragma unroll
        for (int mg = 0; mg < 2; mg++)
            ldm_x4(a[mg], sb + aOff + (uint32_t)((wm + mg * 16 + lrow) * PADK + k0 + lcol8) * 2u);
        uint32_t bh[2][4], bl[2][4];
#pragma unroll
        for (int nc = 0; nc < 2; nc++) {
            uint32_t boff = (uint32_t)((k0 + lrow) * PADK + wn + nc * 16 + lcol8) * 2u;
            ldm_x4_t(bh[nc], sb + bOffH + boff);
            ldm_x4_t(bl[nc], sb + bOffL + boff);
        }
#pragma unroll
        for (int mg = 0; mg < 2; mg++)
#pragma unroll
            for (int ng = 0; ng < 4; ng++) {
                mma_f16(acc[mg][ng], a[mg], &bh[ng >> 1][(ng & 1) * 2]);
                mma_f16(acc[mg][ng], a[mg], &bl[ng >> 1][(ng & 1) * 2]);
            }
    }
}

// 3-term mainloop (A split): acc += Ah*Bh + Ah*Bl + Al*Bh.
__device__ __forceinline__ void mma_loop3(uint32_t sb, int ahOff, int alOff,
                                          int bOffH, int bOffL,
                                          int wm, int wn, int lane,
                                          float acc[2][4][4]) {
    int lrow = lane & 15;
    int lcol8 = (lane >> 4) << 3;
#pragma unroll
    for (int t = 0; t < 3; t++) {
        int aOff = (t == 2) ? alOff : ahOff;
        int bOff = (t == 1) ? bOffL : bOffH;
#pragma unroll
        for (int k0 = 0; k0 < 128; k0 += 16) {
            uint32_t a[2][4];
#pragma unroll
            for (int mg = 0; mg < 2; mg++)
                ldm_x4(a[mg], sb + aOff + (uint32_t)((wm + mg * 16 + lrow) * PADK + k0 + lcol8) * 2u);
            uint32_t b[2][4];
#pragma unroll
            for (int nc = 0; nc < 2; nc++)
                ldm_x4_t(b[nc], sb + bOff + (uint32_t)((k0 + lrow) * PADK + wn + nc * 16 + lcol8) * 2u);
#pragma unroll
            for (int mg = 0; mg < 2; mg++)
#pragma unroll
                for (int ng = 0; ng < 4; ng++)
                    mma_f16(acc[mg][ng], a[mg], &b[ng >> 1][(ng & 1) * 2]);
        }
    }
}

// stage a weight matrix from fp32 gmem, splitting to fp16 hi/lo in smem.
__device__ __forceinline__ void stage_B16(char* sm, int offH, int offL,
                                          const float* __restrict__ W,
                                          const float* rscale, int tid) {
    for (int g = tid; g < 4096; g += 512) {
        int r = g >> 5, c = (g & 31) * 4;
        float4 w = *reinterpret_cast<const float4*>(&W[r * DIM + c]);
        if (rscale) {
            float s = rscale[r];
            w.x *= s; w.y *= s; w.z *= s; w.w *= s;
        }
        uint32_t eoff = (uint32_t)(r * PADK + c) * 2u;
        uint32_t l0, l1;
        uint32_t h0 = pack_hi16(w.x, w.y, l0);
        uint32_t h1 = pack_hi16(w.z, w.w, l1);
        *reinterpret_cast<uint2*>(sm + offH + eoff) = make_uint2(h0, h1);
        *reinterpret_cast<uint2*>(sm + offL + eoff) = make_uint2(l0, l1);
    }
}

// ======================= main GEMM (persistent, fused PairNorm on A) ========
__global__ __launch_bounds__(512) void gemm_mma_k(
    const __half* __restrict__ A, const float* __restrict__ Xold,
    float* __restrict__ Xwrite, const float* __restrict__ Wf32,
    __half* __restrict__ C, int n,
    int pn_slot, int zero_slot, int addold, float n_inv) {
    extern __shared__ char sm[];
    float* smu = reinterpret_cast<float*>(sm + 3 * TILE_B);
    float* red = smu + DIM;
    uint32_t sb = smem_u32(sm);
    int tid = threadIdx.x, wid = tid >> 5, lane = tid & 31;

    if (zero_slot >= 0 && blockIdx.x == 0 && tid < DIM) {
        g_cs[zero_slot][tid] = 0.f;
        g_cq[zero_slot][tid] = 0.f;
    }

    if (tid < DIM) {
        float mu = g_cs[pn_slot][tid] * n_inv;
        smu[tid] = mu;
        red[tid] = g_cq[pn_slot][tid] * n_inv - mu * mu;
    }
    __syncthreads();
    for (int off = 64; off > 0; off >>= 1) {
        if (tid < off) red[tid] += red[tid + off];
        __syncthreads();
    }
    if (tid == 0) red[0] = rsqrtf(1e-6f + red[0]);
    __syncthreads();
    float pscale = red[0];

    int T = (n + 127) >> 7;
    int t = blockIdx.x;
    if (t >= T) return;

    stage_B16(sm, OFF_BH, OFF_BL, Wf32, nullptr, tid);

    {
        int row0 = t * 128;
        for (int g = tid; g < 4096; g += 512) {
            int r = g >> 5, c = (g & 31) * 4;
            int row = row0 + r;
            float4 av = make_float4(0.f, 0.f, 0.f, 0.f);
            if (row < n) {
                av = h4_to_f4(*reinterpret_cast<const uint2*>(&A[(size_t)row * DIM + c]));
                float4 m = *reinterpret_cast<const float4*>(&smu[c]);
                av.x = fmaxf((av.x - m.x) * pscale, 0.f);
                av.y = fmaxf((av.y - m.y) * pscale, 0.f);
                av.z = fmaxf((av.z - m.z) * pscale, 0.f);
                av.w = fmaxf((av.w - m.w) * pscale, 0.f);
                if (addold) {
                    float4 xo = *reinterpret_cast<const float4*>(&Xold[(size_t)row * DIM + c]);
                    av.x += xo.x; av.y += xo.y; av.z += xo.z; av.w += xo.w;
                }
                *reinterpret_cast<float4*>(&Xwrite[(size_t)row * DIM + c]) = av;
            }
            __half2 p0 = __floats2half2_rn(av.x, av.y);
            __half2 p1 = __floats2half2_rn(av.z, av.w);
            uint32_t eoff = (uint32_t)(r * PADK + c) * 2u;
            *reinterpret_cast<uint2*>(sm + OFF_A + eoff) =
                make_uint2(*reinterpret_cast<uint32_t*>(&p0), *reinterpret_cast<uint32_t*>(&p1));
        }
    }
    __syncthreads();

    int wm = (wid & 3) * 32;
    int wn = (wid >> 2) * 32;

    while (true) {
        int tn = t + gridDim.x;
        bool hn = tn < T;
        uint2 raw[8];
        if (hn) {
            int row0n = tn * 128;
#pragma unroll
            for (int q = 0; q < 8; q++) {
                int g = q * 512 + tid;
                int r = g >> 5, c = (g & 31) * 4;
                int row = row0n + r;
                raw[q] = (row < n)
                    ? *reinterpret_cast<const uint2*>(&A[(size_t)row * DIM + c])
                    : make_uint2(0u, 0u);
            }
        }

        float acc[2][4][4];
#pragma unroll
        for (int mg = 0; mg < 2; mg++)
#pragma unroll
            for (int ng = 0; ng < 4; ng++)
#pragma unroll
                for (int q = 0; q < 4; q++) acc[mg][ng][q] = 0.f;

        mma_loop2(sb, OFF_A, OFF_BH, OFF_BL, wm, wn, lane, acc);

        int row0 = t * 128;
        int rbase = row0 + wm + (lane >> 2);
        int cbase = wn + (lane & 3) * 2;
#pragma unroll
        for (int mg = 0; mg < 2; mg++)
#pragma unroll
            for (int half = 0; half < 2; half++) {
                int row = rbase + mg * 16 + half * 8;
                if (row < n) {
#pragma unroll
                    for (int ng = 0; ng < 4; ng++) {
                        int col = cbase + ng * 8;
                        __half2 o = __floats2half2_rn(acc[mg][ng][half * 2],
                                                      acc[mg][ng][half * 2 + 1]);
                        *reinterpret_cast<__half2*>(&C[(size_t)row * DIM + col]) = o;
                    }
                }
            }

        if (!hn) break;
        __syncthreads();
        {
            int row0n = tn * 128;
#pragma unroll
            for (int q = 0; q < 8; q++) {
                int g = q * 512 + tid;
                int r = g >> 5, c = (g & 31) * 4;
                int row = row0n + r;
                float4 av = make_float4(0.f, 0.f, 0.f, 0.f);
                if (row < n) {
                    av = h4_to_f4(raw[q]);
                    float4 m = *reinterpret_cast<const float4*>(&smu[c]);
                    av.x = fmaxf((av.x - m.x) * pscale, 0.f);
                    av.y = fmaxf((av.y - m.y) * pscale, 0.f);
                    av.z = fmaxf((av.z - m.z) * pscale, 0.f);
                    av.w = fmaxf((av.w - m.w) * pscale, 0.f);
                    if (addold) {
                        float4 xo = *reinterpret_cast<const float4*>(&Xold[(size_t)row * DIM + c]);
                        av.x += xo.x; av.y += xo.y; av.z += xo.z; av.w += xo.w;
                    }
                    *reinterpret_cast<float4*>(&Xwrite[(size_t)row * DIM + c]) = av;
                }
                __half2 p0 = __floats2half2_rn(av.x, av.y);
                __half2 p1 = __floats2half2_rn(av.z, av.w);
                uint32_t eoff = (uint32_t)(r * PADK + c) * 2u;
                *reinterpret_cast<uint2*>(sm + OFF_A + eoff) =
                    make_uint2(*reinterpret_cast<uint32_t*>(&p0), *reinterpret_cast<uint32_t*>(&p1));
            }
        }
        __syncthreads();
        t = tn;
    }
}

// ======================= fused fc_in + layer-0 GEMM (persistent) ============
__global__ __launch_bounds__(512) void gemm_fused_k(
    const float* __restrict__ X,
    const float* __restrict__ fin_w, const float* __restrict__ fin_b,
    const float* __restrict__ gamma, const float* __restrict__ beta,
    const float* __restrict__ W2,
    __half* __restrict__ C, int n, float n_inv) {
    extern __shared__ char sm[];
    float* ssc = reinterpret_cast<float*>(sm + 6 * TILE_B);
    float* ssh = ssc + DIM;
    float* sbias = ssh + DIM;
    uint32_t sb = smem_u32(sm);
    int tid = threadIdx.x, wid = tid >> 5, lane = tid & 31;

    if (blockIdx.x == 0 && tid < DIM) {
        g_cs[0][tid] = 0.f;
        g_cq[0][tid] = 0.f;
    }
    if (tid < DIM) {
        float s0 = 0.f, s1 = 0.f, s2 = 0.f, s3 = 0.f;
        float q0 = 0.f, q1 = 0.f, q2 = 0.f, q3 = 0.f;
        for (int p = 0; p < 256; p += 4) {
            s0 += g_bn_ps[p][tid];     s1 += g_bn_ps[p + 1][tid];
            s2 += g_bn_ps[p + 2][tid]; s3 += g_bn_ps[p + 3][tid];
            q0 += g_bn_pq[p][tid];     q1 += g_bn_pq[p + 1][tid];
            q2 += g_bn_pq[p + 2][tid]; q3 += g_bn_pq[p + 3][tid];
        }
        float mu = ((s0 + s1) + (s2 + s3)) * n_inv;
        float var = ((q0 + q1) + (q2 + q3)) * n_inv - mu * mu;
        float s = gamma[tid] * rsqrtf(var + 1e-5f);
        ssc[tid] = s;
        ssh[tid] = beta[tid] - mu * s;
    }
    __syncthreads();

    int T = (n + 127) >> 7;
    int t = blockIdx.x;
    if (t >= T) return;

    stage_B16(sm, F_B1H, F_B1L, fin_w, ssc, tid);
    stage_B16(sm, F_B2H, F_B2L, W2, nullptr, tid);
    if (tid < DIM) {
        float acc = fin_b[tid];
        for (int d = 0; d < DIM; d++) acc += ssh[d] * fin_w[d * DIM + tid];
        sbias[tid] = acc;
    }

    {
        int row0 = t * 128;
        for (int g = tid; g < 4096; g += 512) {
            int r = g >> 5, c = (g & 31) * 4;
            int row = row0 + r;
            float4 av = make_float4(0.f, 0.f, 0.f, 0.f);
            if (row < n) av = *reinterpret_cast<const float4*>(&X[(size_t)row * DIM + c]);
            uint32_t eoff = (uint32_t)(r * PADK + c) * 2u;
            uint32_t al0, al1;
            uint32_t ah0 = pack_hi16(av.x, av.y, al0);
            uint32_t ah1 = pack_hi16(av.z, av.w, al1);
            *reinterpret_cast<uint2*>(sm + F_AH + eoff) = make_uint2(ah0, ah1);
            *reinterpret_cast<uint2*>(sm + F_AL + eoff) = make_uint2(al0, al1);
        }
    }
    __syncthreads();

    int wm = (wid & 3) * 32;
    int wn = (wid >> 2) * 32;

    while (true) {
        int tn = t + gridDim.x;
        bool hn = tn < T;
        float4 raw[8];
        if (hn) {
            int row0n = tn * 128;
#pragma unroll
            for (int q = 0; q < 8; q++) {
                int g = q * 512 + tid;
                int r = g >> 5, c = (g & 31) * 4;
                int row = row0n + r;
                raw[q] = (row < n)
                    ? *reinterpret_cast<const float4*>(&X[(size_t)row * DIM + c])
                    : make_float4(0.f, 0.f, 0.f, 0.f);
            }
        }

        float acc[2][4][4];
#pragma unroll
        for (int mg = 0; mg < 2; mg++)
#pragma unroll
            for (int ng = 0; ng < 4; ng++)
#pragma unroll
                for (int q = 0; q < 4; q++) acc[mg][ng][q] = 0.f;

        mma_loop3(sb, F_AH, F_AL, F_B1H, F_B1L, wm, wn, lane, acc);
        __syncthreads();

        {
            int rl = wm + (lane >> 2);
            int cb = wn + (lane & 3) * 2;
#pragma unroll
            for (int mg = 0; mg < 2; mg++)
#pragma unroll
                for (int half = 0; half < 2; half++) {
                    int r = rl + mg * 16 + half * 8;
#pragma unroll
                    for (int ng = 0; ng < 4; ng++) {
                        int col = cb + ng * 8;
                        float v0 = acc[mg][ng][half * 2] + sbias[col];
                        float v1 = acc[mg][ng][half * 2 + 1] + sbias[col + 1];
                        __half2 p = __floats2half2_rn(v0, v1);
                        uint32_t eoff = (uint32_t)(r * PADK + col) * 2u;
                        *reinterpret_cast<uint32_t*>(sm + F_AH + eoff) =
                            *reinterpret_cast<uint32_t*>(&p);
                    }
                }
        }
        __syncthreads();

#pragma unroll
        for (int mg = 0; mg < 2; mg++)
#pragma unroll
            for (int ng = 0; ng < 4; ng++)
#pragma unroll
                for (int q = 0; q < 4; q++) acc[mg][ng][q] = 0.f;

        mma_loop2(sb, F_AH, F_B2H, F_B2L, wm, wn, lane, acc);

        int row0 = t * 128;
        int rbase = row0 + wm + (lane >> 2);
        int cbase = wn + (lane & 3) * 2;
#pragma unroll
        for (int mg = 0; mg < 2; mg++)
#pragma unroll
            for (int half = 0; half < 2; half++) {
                int row = rbase + mg * 16 + half * 8;
                if (row < n) {
#pragma unroll
                    for (int ng = 0; ng < 4; ng++) {
                        int col = cbase + ng * 8;
                        __half2 o = __floats2half2_rn(acc[mg][ng][half * 2],
                                                      acc[mg][ng][half * 2 + 1]);
                        *reinterpret_cast<__half2*>(&C[(size_t)row * DIM + col]) = o;
                    }
                }
            }

        if (!hn) break;
        __syncthreads();
        {
#pragma unroll
            for (int q = 0; q < 8; q++) {
                int g = q * 512 + tid;
                int r = g >> 5, c = (g & 31) * 4;
                float4 av = raw[q];
                uint32_t eoff = (uint32_t)(r * PADK + c) * 2u;
                uint32_t al0, al1;
                uint32_t ah0 = pack_hi16(av.x, av.y, al0);
                uint32_t ah1 = pack_hi16(av.z, av.w, al1);
                *reinterpret_cast<uint2*>(sm + F_AH + eoff) = make_uint2(ah0, ah1);
                *reinterpret_cast<uint2*>(sm + F_AL + eoff) = make_uint2(al0, al1);
            }
        }
        __syncthreads();
        t = tn;
    }
}

// ======================= input BN stats -> per-block partials ===============
__global__ __launch_bounds__(256) void col_stats_k(const float* __restrict__ x, int n) {
    __shared__ float red[256];
    __shared__ float redq[128];
    int tid = threadIdx.x;
    red[tid] = 0.f;
    if (tid < 128) redq[tid] = 0.f;
    int w = tid >> 5, lane = tid & 31, c = lane * 4;
    int gw = blockIdx.x * 8 + w;
    const int STR = 256 * 8;
    float4 s = make_float4(0.f, 0.f, 0.f, 0.f);
    float4 q = make_float4(0.f, 0.f, 0.f, 0.f);
    __syncthreads();
    for (int r0 = gw; r0 < n; r0 += STR * 4) {
#pragma unroll
        for (int u = 0; u < 4; u++) {
            int row = r0 + u * STR;
            if (row < n) {
                float4 v = *reinterpret_cast<const float4*>(&x[(size_t)row * DIM + c]);
                s.x += v.x; s.y += v.y; s.z += v.z; s.w += v.w;
                q.x += v.x * v.x; q.y += v.y * v.y; q.z += v.z * v.z; q.w += v.w * v.w;
            }
        }
    }
    atomicAdd(&red[c], s.x);     atomicAdd(&red[c + 1], s.y);
    atomicAdd(&red[c + 2], s.z); atomicAdd(&red[c + 3], s.w);
    atomicAdd(&redq[c], q.x);     atomicAdd(&redq[c + 1], q.y);
    atomicAdd(&redq[c + 2], q.z); atomicAdd(&redq[c + 3], q.w);
    __syncthreads();
    if (tid < 128) {
        g_bn_ps[blockIdx.x][tid] = red[tid];
        g_bn_pq[blockIdx.x][tid] = redq[tid];
    }
}

// ======================= CSR build ==========================================
__global__ void hist_k(const int* __restrict__ er, int e) {
    int i = blockIdx.x * blockDim.x + threadIdx.x;
    if (i < e) atomicAdd(&g_cnt[er[i]], 1);
}

__global__ __launch_bounds__(256) void scan1_k(int n) {
    __shared__ int red[256];
    int tid = threadIdx.x;
    int i = blockIdx.x * 256 + tid;
    red[tid] = (i < n) ? g_cnt[i] : 0;
    __syncthreads();
    for (int off = 128; off > 0; off >>= 1) {
        if (tid < off) red[tid] += red[tid + off];
        __syncthreads();
    }
    if (tid == 0) g_bsum[blockIdx.x] = red[0];
}

__global__ __launch_bounds__(256) void scan3_k(int n, int nblk) {
    __shared__ int bs[256];
    __shared__ int s[256];
    int tid = threadIdx.x;
    bs[tid] = (tid < nblk) ? g_bsum[tid] : 0;
    __syncthreads();
    for (int off = 1; off < 256; off <<= 1) {
        int t = (tid >= off) ? bs[tid - off] : 0;
        __syncthreads();
        bs[tid] += t;
        __syncthreads();
    }
    int bpref = (blockIdx.x == 0) ? 0 : bs[blockIdx.x - 1];
    if (blockIdx.x == 0 && tid == 0) g_rowptr[n] = bs[255];
    int i = blockIdx.x * 256 + tid;
    int v = (i < n) ? g_cnt[i] : 0;
    s[tid] = v;
    __syncthreads();
    for (int off = 1; off < 256; off <<= 1) {
        int t = (tid >= off) ? s[tid - off] : 0;
        __syncthreads();
        s[tid] += t;
        __syncthreads();
    }
    if (i < n) {
        int excl = s[tid] - v + bpref;
        g_rowptr[i] = excl;
        g_wcur[i] = excl;
        g_cnt[i] = 0;
    }
}

__global__ void scatter_k(const int* __restrict__ er, const int* __restrict__ ec,
                          const float* __restrict__ ev, int e) {
    int i = blockIdx.x * blockDim.x + threadIdx.x;
    if (i < e) {
        int r = er[i];
        int pos = atomicAdd(&g_wcur[r], 1);
        g_edge[pos] = make_int2(ec[i], __float_as_int(ev[i]));
    }
}

// ======================= SPMM (fp16 in/out) + fused PairNorm stats ==========
// Software-pipelined 4-edge groups: loads for group k+1 issue before FMAs of
// group k (in-order issue => explicit reordering keeps gathers in flight).
#define SPMM_LD(P, V, base)                                                    \
    do {                                                                       \
        _Pragma("unroll")                                                      \
        for (int u = 0; u < 4; u++) {                                          \
            int2 ed = g_edge[(base) + u];                                      \
            (V)[u] = __int_as_float(ed.y);                                     \
            (P)[u] = *reinterpret_cast<const uint2*>(&g[(size_t)ed.x * DIM + c]); \
        }                                                                      \
    } while (0)
#define SPMM_FMA(P, V)                                                         \
    do {                                                                       \
        _Pragma("unroll")                                                      \
        for (int u = 0; u < 4; u++) {                                          \
            float4 gv = h4_to_f4((P)[u]);                                      \
            acc.x += (V)[u] * gv.x;                                            \
            acc.y += (V)[u] * gv.y;                                            \
            acc.z += (V)[u] * gv.z;                                            \
            acc.w += (V)[u] * gv.w;                                            \
        }                                                                      \
    } while (0)

__global__ __launch_bounds__(256) void spmm_k(
    const __half* __restrict__ g, const float* __restrict__ bias,
    __half* __restrict__ h, int n, int slot) {
    __shared__ float red[256];
    int tid = threadIdx.x;
    red[tid] = 0.f;
    int w = tid >> 5, lane = tid & 31;
    int gw = blockIdx.x * 8 + w;
    int c = lane * 4;
    float4 b4 = *reinterpret_cast<const float4*>(&bias[c]);
    float4 ssum = make_float4(0.f, 0.f, 0.f, 0.f);
    float4 ssq = make_float4(0.f, 0.f, 0.f, 0.f);
    __syncthreads();
#pragma unroll
    for (int rr = 0; rr < 4; rr++) {
        int row = gw * 4 + rr;
        if (row >= n) break;
        int s = g_rowptr[row];
        int e = g_rowptr[row + 1];
        float4 acc = make_float4(0.f, 0.f, 0.f, 0.f);
        int i = s;
        uint2 pa[4], pb[4];
        float va[4], vb[4];
        if (i + 4 <= e) {
            SPMM_LD(pa, va, i);
            i += 4;
            while (true) {
                if (i + 4 <= e) {               // load B, fma A
                    SPMM_LD(pb, vb, i);
                    i += 4;
                    SPMM_FMA(pa, va);
                } else {
                    SPMM_FMA(pa, va);
                    break;
                }
                if (i + 4 <= e) {               // load A, fma B
                    SPMM_LD(pa, va, i);
                    i += 4;
                    SPMM_FMA(pb, vb);
                } else {
                    SPMM_FMA(pb, vb);
                    break;
                }
            }
        }
        for (; i < e; i++) {
            int2 ed = g_edge[i];
            float v0 = __int_as_float(ed.y);
            float4 gv = h4_to_f4(*reinterpret_cast<const uint2*>(&g[(size_t)ed.x * DIM + c]));
            acc.x += v0 * gv.x; acc.y += v0 * gv.y;
            acc.z += v0 * gv.z; acc.w += v0 * gv.w;
        }
        acc.x += b4.x; acc.y += b4.y; acc.z += b4.z; acc.w += b4.w;
        __half2 o0 = __floats2half2_rn(acc.x, acc.y);
        __half2 o1 = __floats2half2_rn(acc.z, acc.w);
        uint2 ov;
        ov.x = *reinterpret_cast<uint32_t*>(&o0);
        ov.y = *reinterpret_cast<uint32_t*>(&o1);
        *reinterpret_cast<uint2*>(&h[(size_t)row * DIM + c]) = ov;
        ssum.x += acc.x; ssum.y += acc.y; ssum.z += acc.z; ssum.w += acc.w;
        ssq.x += acc.x * acc.x; ssq.y += acc.y * acc.y;
        ssq.z += acc.z * acc.z; ssq.w += acc.w * acc.w;
    }
    atomicAdd(&red[c], ssum.x);     atomicAdd(&red[c + 1], ssum.y);
    atomicAdd(&red[c + 2], ssum.z); atomicAdd(&red[c + 3], ssum.w);
    atomicAdd(&red[128 + c], ssq.x);     atomicAdd(&red[128 + c + 1], ssq.y);
    atomicAdd(&red[128 + c + 2], ssq.z); atomicAdd(&red[128 + c + 3], ssq.w);
    __syncthreads();
    if (tid < 128) atomicAdd(&g_cs[slot][tid], red[tid]);
    else atomicAdd(&g_cq[slot][tid - 128], red[tid]);
}

// ======================= output GEMM + fused final PairNorm =================
__global__ __launch_bounds__(256) void gemm_out_k(
    const __half* __restrict__ H, const float* __restrict__ Xold,
    const float* __restrict__ W, const float* __restrict__ b,
    float* __restrict__ out, int n, int pn_slot, float n_inv) {
    __shared__ float sx[32 * DIM];
    __shared__ float sw[DIM * CDIM];
    __shared__ float smu[DIM];
    __shared__ float red[DIM];
    int tid = threadIdx.x;
    int row0 = blockIdx.x * 32;
    for (int i = tid; i < DIM * CDIM; i += 256) sw[i] = W[i];
    if (tid < DIM) {
        float mu = g_cs[pn_slot][tid] * n_inv;
        smu[tid] = mu;
        red[tid] = g_cq[pn_slot][tid] * n_inv - mu * mu;
    }
    __syncthreads();
    for (int off = 64; off > 0; off >>= 1) {
        if (tid < off) red[tid] += red[tid + off];
        __syncthreads();
    }
    if (tid == 0) red[0] = rsqrtf(1e-6f + red[0]);
    __syncthreads();
    float s = red[0];
#pragma unroll
    for (int q = 0; q < 4; q++) {
        int flat = (q * 256 + tid) * 4;
        int r = flat >> 7, c = flat & 127;
        int row = row0 + r;
        float4 v = make_float4(0.f, 0.f, 0.f, 0.f);
        if (row < n) {
            float4 hv = h4_to_f4(*reinterpret_cast<const uint2*>(&H[(size_t)row * DIM + c]));
            float4 m = *reinterpret_cast<const float4*>(&smu[c]);
            float4 xo = *reinterpret_cast<const float4*>(&Xold[(size_t)row * DIM + c]);
            v.x = fmaxf((hv.x - m.x) * s, 0.f) + xo.x;
            v.y = fmaxf((hv.y - m.y) * s, 0.f) + xo.y;
            v.z = fmaxf((hv.z - m.z) * s, 0.f) + xo.z;
            v.w = fmaxf((hv.w - m.w) * s, 0.f) + xo.w;
        }
        *reinterpret_cast<float4*>(&sx[flat]) = v;
    }
    __syncthreads();
    int r = tid >> 3;
    int c0 = (tid & 7) * 5;
    float acc[5];
#pragma unroll
    for (int j = 0; j < 5; j++) acc[j] = b[c0 + j];
#pragma unroll 4
    for (int k = 0; k < DIM; k++) {
        float xv = sx[r * DIM + k];
#pragma unroll
        for (int j = 0; j < 5; j++) acc[j] += xv * sw[k * CDIM + c0 + j];
    }
    if (row0 + r < n) {
#pragma unroll
        for (int j = 0; j < 5; j++) out[(size_t)(row0 + r) * CDIM + c0 + j] = acc[j];
    }
}

// ======================= launch =============================================
extern "C" void kernel_launch(void* const* d_in, const int* in_sizes, int n_in,
                              void* d_out, int out_size) {
    const float* x      = (const float*)d_in[0];
    const int*   er     = (const int*)d_in[1];
    const int*   ec     = (const int*)d_in[2];
    const float* ev     = (const float*)d_in[3];
    const float* gamma  = (const float*)d_in[4];
    const float* beta   = (const float*)d_in[5];
    const float* fin_w  = (const float*)d_in[6];
    const float* fin_b  = (const float*)d_in[7];
    const float* gc_w   = (const float*)d_in[8];
    const float* gc_b   = (const float*)d_in[9];
    const float* fout_w = (const float*)d_in[10];
    const float* fout_b = (const float*)d_in[11];
    float* out = (float*)d_out;

    int n = in_sizes[0] / DIM;
    int e = in_sizes[1];
    float n_inv = 1.0f / (float)n;

    float* xbuf;
    __half *g16, *h16;
    cudaGetSymbolAddress((void**)&xbuf, g_xbuf);
    cudaGetSymbolAddress((void**)&g16, g_g16);
    cudaGetSymbolAddress((void**)&h16, g_h16);

    static cudaStream_t s2 = nullptr;
    static cudaEvent_t evFork = nullptr, evJoin = nullptr;
    if (s2 == nullptr) {
        cudaStreamCreateWithFlags(&s2, cudaStreamNonBlocking);
        cudaEventCreateWithFlags(&evFork, cudaEventDisableTiming);
        cudaEventCreateWithFlags(&evJoin, cudaEventDisableTiming);
        cudaFuncSetAttribute(gemm_mma_k, cudaFuncAttributeMaxDynamicSharedMemorySize, GEMM_SMEM_BYTES);
        cudaFuncSetAttribute(gemm_fused_k, cudaFuncAttributeMaxDynamicSharedMemorySize, FUSED_SMEM_BYTES);
    }

    int sblocks = (n + 31) / 32;     // spmm: 8 warps x 4 rows per block
    int nblk = (n + 255) / 256;
    int eblk = (e + 255) / 256;
    const int WMAT = DIM * DIM;

    // ---- fork: branch B (BN stats -> fused GEMM) concurrent with CSR build
    cudaEventRecord(evFork, 0);
    cudaStreamWaitEvent(s2, evFork, 0);

    // branch B (stream s2)
    col_stats_k<<<256, 256, 0, s2>>>(x, n);
    gemm_fused_k<<<NSM, 512, FUSED_SMEM_BYTES, s2>>>(
        x, fin_w, fin_b, gamma, beta, gc_w, g16, n, n_inv);

    // main stream: CSR build
    hist_k<<<eblk, 256>>>(er, e);
    scan1_k<<<nblk, 256>>>(n);
    scan3_k<<<nblk, 256>>>(n, nblk);
    scatter_k<<<eblk, 256>>>(er, ec, ev, e);

    // ---- join
    cudaEventRecord(evJoin, s2);
    cudaStreamWaitEvent(0, evJoin, 0);

    // ---- layer 0 spmm ----
    spmm_k<<<sblocks, 256>>>(g16, gc_b + 0 * DIM, h16, n, 0);

    // ---- layers 1..3: persistent GEMM with fused PairNorm-apply on A ----
    for (int i = 1; i < NLAYER; i++) {
        gemm_mma_k<<<NSM, 512, GEMM_SMEM_BYTES>>>(
            h16, xbuf, xbuf, gc_w + i * WMAT,
            g16, n, (i - 1) & 1, i & 1, (i >= 2) ? 1 : 0, n_inv);
        spmm_k<<<sblocks, 256>>>(g16, gc_b + i * DIM, h16, n, i & 1);
    }

    // ---- output projection with fused final PairNorm (slot 1, addold) ----
    gemm_out_k<<<sblocks, 256>>>(h16, xbuf, fout_w, fout_b, out, n, (NLAYER - 1) & 1, n_inv);
}